// round 9
// baseline (speedup 1.0000x reference)
#include <cuda_runtime.h>
#include <cstdint>

#define N_NODES 50000
#define N_EDGES 800000
#define FDIM 64
#define N_TILES ((N_NODES + 31) / 32)   // 1563

// ---------------- device scratch ----------------
__device__ int   g_src[N_EDGES];
__device__ int   g_dst[N_EDGES];
__device__ int   g_csrc[N_EDGES];          // CSR: src ids grouped by dst
__device__ int   g_row[N_NODES];           // CSR slice start per dst (arbitrary order)
__device__ int   g_cnt[N_NODES + 1];       // in-degree histogram; [N] = global offset counter
__device__ int   g_cur[N_NODES];           // scatter cursors
__device__ __align__(16) float g_aggG[N_NODES * FDIM];
__device__ __align__(16) float g_aggA[N_NODES * FDIM];
__device__ __align__(16) float g_aggS[N_NODES * FDIM];
__device__ float g_ssrc[N_NODES];
__device__ float g_sdst[N_NODES];
__device__ float g_dinv[N_NODES];

__device__ __forceinline__ float lrelu(float v) { return v > 0.f ? v : 0.2f * v; }

// ---- packed f32x2 helpers (sm_100+: SASS FFMA2; only reachable via PTX) ----
__device__ __forceinline__ unsigned long long pack2(float lo, float hi) {
    unsigned long long r;
    asm("mov.b64 %0, {%1, %2};" : "=l"(r) : "f"(lo), "f"(hi));
    return r;
}
__device__ __forceinline__ unsigned long long fma2(unsigned long long a, unsigned long long b,
                                                   unsigned long long c) {
    unsigned long long d;
    asm("fma.rn.f32x2 %0, %1, %2, %3;" : "=l"(d) : "l"(a), "l"(b), "l"(c));
    return d;
}
__device__ __forceinline__ void unpack2(unsigned long long v, float& lo, float& hi) {
    asm("mov.b64 {%0, %1}, %2;" : "=f"(lo), "=f"(hi) : "l"(v));
}

// ---------------- 0: dtype-detect + convert + histogram + per-node attn scalars ----------------
// int64 detection: ids < 50000 so high 32-bit words are 0; if int32, the odd
// words are 64 random ids (all-zero prob ~ (1/50000)^64 ~ 0).
__global__ void k_convert(const void* __restrict__ ei, const float* __restrict__ x,
                          const float* __restrict__ Wa, const float* __restrict__ as_,
                          const float* __restrict__ ad_) {
    __shared__ int s_is64;
    __shared__ float sva[FDIM], svb[FDIM];
    const unsigned int* w = (const unsigned int*)ei;
    int gid = blockIdx.x * blockDim.x + threadIdx.x;

    if (threadIdx.x == 0) {
        int z = 1;
        for (int i = 0; i < 64; i++) if (w[2 * i + 1] != 0u) { z = 0; break; }
        s_is64 = z;
    }
    if (blockIdx.x * blockDim.x < N_NODES) {
        if (threadIdx.x < FDIM) {
            int k = threadIdx.x;
            float va = 0.f, vb = 0.f;
            #pragma unroll 8
            for (int j = 0; j < FDIM; j++) {
                float wv = Wa[k * FDIM + j];
                va = fmaf(wv, as_[j], va);
                vb = fmaf(wv, ad_[j], vb);
            }
            sva[k] = va;
            svb[k] = vb;
        }
        __syncthreads();
        if (gid < N_NODES) {
            const float4* xr = (const float4*)(x + (size_t)gid * FDIM);
            float ss = 0.f, sd = 0.f;
            #pragma unroll
            for (int i = 0; i < FDIM / 4; i++) {
                float4 v = xr[i];
                ss = fmaf(v.x, sva[4*i], fmaf(v.y, sva[4*i+1], fmaf(v.z, sva[4*i+2], fmaf(v.w, sva[4*i+3], ss))));
                sd = fmaf(v.x, svb[4*i], fmaf(v.y, svb[4*i+1], fmaf(v.z, svb[4*i+2], fmaf(v.w, svb[4*i+3], sd))));
            }
            g_ssrc[gid] = ss;
            g_sdst[gid] = sd;
        }
    } else {
        __syncthreads();
    }
    int is64 = s_is64;
    int stride = gridDim.x * blockDim.x;
    for (int i = gid; i < 2 * N_EDGES; i += stride) {
        int v;
        if (is64) v = (int)((const long long*)ei)[i];
        else      v = ((const int*)ei)[i];
        if (i < N_EDGES) g_src[i] = v;
        else {
            g_dst[i - N_EDGES] = v;
            atomicAdd(&g_cnt[v], 1);
        }
    }
}

// ---------------- 1: row-slice assignment (block scan + 1 atomic per block) ----------------
__global__ void k_rowassign() {
    __shared__ int s_warp[8];
    __shared__ int s_base;
    int tid = threadIdx.x;
    int n = blockIdx.x * 256 + tid;
    int lane = tid & 31, wid = tid >> 5;
    int c = (n < N_NODES) ? g_cnt[n] : 0;
    int v = c;
    #pragma unroll
    for (int off = 1; off < 32; off <<= 1) {
        int u = __shfl_up_sync(0xffffffffu, v, off);
        if (lane >= off) v += u;
    }
    if (lane == 31) s_warp[wid] = v;
    __syncthreads();
    if (tid < 8) {
        int pv = s_warp[tid];
        #pragma unroll
        for (int off = 1; off < 8; off <<= 1) {
            int u = __shfl_up_sync(0xffu, pv, off);
            if (tid >= off) pv += u;
        }
        s_warp[tid] = pv;
        if (tid == 7) s_base = atomicAdd(&g_cnt[N_NODES], pv);
    }
    __syncthreads();
    int excl = v - c + (wid > 0 ? s_warp[wid - 1] : 0);
    if (n < N_NODES) {
        g_row[n] = s_base + excl;
        g_cur[n] = 0;
        g_dinv[n] = rsqrtf((float)c + 1.0f);
    }
}

// ---------------- 2: scatter src into CSR ----------------
__global__ void k_scatter() {
    int stride = gridDim.x * blockDim.x;
    for (int e = blockIdx.x * blockDim.x + threadIdx.x; e < N_EDGES; e += stride) {
        int d = g_dst[e];
        int pos = g_row[d] + atomicAdd(&g_cur[d], 1);
        g_csrc[pos] = g_src[e];
    }
}

// ---------------- 3: warp-per-node aggregation (R5 shuffle version — 40 regs, high occ) ----------------
__global__ void __launch_bounds__(256) k_agg(const float* __restrict__ x) {
    int wid = (blockIdx.x * blockDim.x + threadIdx.x) >> 5;
    int lane = threadIdx.x & 31;
    if (wid >= N_NODES) return;
    int d = wid;
    int row = g_row[d], end = row + g_cnt[d];
    float sd = g_sdst[d];
    float dvd = g_dinv[d];
    int q = lane & 15, half = lane >> 4;

    float4 aG = make_float4(0.f, 0.f, 0.f, 0.f);
    float4 aA = aG, aS = aG;
    float denom = 0.f;

    for (int base = row; base < end; base += 32) {
        int m = min(32, end - base);
        int   s_r = 0;
        float we_r = 0.f, wg_r = 0.f;
        if (lane < m) {
            s_r = g_csrc[base + lane];
            we_r = expf(lrelu(g_ssrc[s_r] + sd));
            wg_r = g_dinv[s_r] * dvd;
            denom += we_r;
        }
        for (int i2 = 0; i2 < m; i2 += 2) {
            int i = i2 + half;
            int ic = (i < m) ? i : 0;
            int   s  = __shfl_sync(0xffffffffu, s_r, ic);
            float we = __shfl_sync(0xffffffffu, we_r, ic);
            float wg = __shfl_sync(0xffffffffu, wg_r, ic);
            if (i < m) {
                float4 xv = ((const float4*)x)[s * 16 + q];
                aG.x = fmaf(wg, xv.x, aG.x); aG.y = fmaf(wg, xv.y, aG.y);
                aG.z = fmaf(wg, xv.z, aG.z); aG.w = fmaf(wg, xv.w, aG.w);
                aA.x = fmaf(we, xv.x, aA.x); aA.y = fmaf(we, xv.y, aA.y);
                aA.z = fmaf(we, xv.z, aA.z); aA.w = fmaf(we, xv.w, aA.w);
                aS.x += xv.x; aS.y += xv.y; aS.z += xv.z; aS.w += xv.w;
            }
        }
    }

    #pragma unroll
    for (int off = 16; off > 0; off >>= 1)
        denom += __shfl_xor_sync(0xffffffffu, denom, off);
    float selfexp = expf(lrelu(g_ssrc[d] + sd));
    float rdenom = 1.0f / (denom + selfexp);

    #pragma unroll
    for (int c = 0; c < 12; c++) {
        float* p = (c < 4) ? (&aG.x + c) : (c < 8) ? (&aA.x + (c - 4)) : (&aS.x + (c - 8));
        *p += __shfl_xor_sync(0xffffffffu, *p, 16);
    }
    if (half == 0) {
        float4 xd = ((const float4*)x)[d * 16 + q];
        float wd = dvd * dvd;
        float4 G = make_float4(fmaf(wd, xd.x, aG.x), fmaf(wd, xd.y, aG.y),
                               fmaf(wd, xd.z, aG.z), fmaf(wd, xd.w, aG.w));
        float4 A = make_float4((aA.x + selfexp * xd.x) * rdenom, (aA.y + selfexp * xd.y) * rdenom,
                               (aA.z + selfexp * xd.z) * rdenom, (aA.w + selfexp * xd.w) * rdenom);
        ((float4*)g_aggG)[d * 16 + q] = G;
        ((float4*)g_aggA)[d * 16 + q] = A;
        ((float4*)g_aggS)[d * 16 + q] = aS;
    }
}

// ---------------- 4: 5-panel GEMM with packed FFMA2, 640 threads ----------------
// panels: 0: aggG@Wg  1: aggA@Wa  2: (aggS*ci)@Wl  3: x@Wr  4: (x+aggS)@Wi
// 20 warps = 5 panels x 4 node-groups(8). Thread tile: 2 nodes x 8 outs (outs packed f32x2).
// smem float layout:
//   sW   [5][64][64]      @ 0        (20480)
//   sWo  [4][64]          @ 20480    (256)
//   sBias[4][64]          @ 20736    (256)
//   sU   [5][64][32]      @ 20992    (10240)  inputs transposed [k][node]
//   sP   [5][32][66]      @ 31232    (10560)  panel outputs, even padding for b64 stores
//   sCi  [32]             @ 41792    (32)
#define KF_SMEM_FLOATS 41824
#define KF_SMEM_BYTES (KF_SMEM_FLOATS * 4)

__global__ void __launch_bounds__(640, 1) k_final(
        const float* __restrict__ x,
        const float* __restrict__ Wg, const float* __restrict__ bg,
        const float* __restrict__ Wa, const float* __restrict__ ba,
        const float* __restrict__ Wl, const float* __restrict__ bl,
        const float* __restrict__ Wr,
        const float* __restrict__ Wi, const float* __restrict__ bi,
        const float* __restrict__ Wo, const float* __restrict__ bo,
        float* __restrict__ out) {
    extern __shared__ float sm[];
    float* sW   = sm;
    float* sWo  = sm + 20480;
    float* sBia = sm + 20736;
    float* sU   = sm + 20992;
    float* sP   = sm + 31232;
    float* sCi  = sm + 41792;
    int tid = threadIdx.x;

    for (int i = tid; i < 4096; i += 640) {
        sW[i]            = Wg[i];
        sW[4096 + i]     = Wa[i];
        sW[2 * 4096 + i] = Wl[i];
        sW[3 * 4096 + i] = Wr[i];
        sW[4 * 4096 + i] = Wi[i];
    }
    if (tid < 256) sWo[tid] = Wo[tid];
    if (tid < 64) {
        sBia[tid] = bg[tid]; sBia[64 + tid] = ba[tid];
        sBia[128 + tid] = bl[tid]; sBia[192 + tid] = bi[tid];
    }
    float bout = bo[0];
    __syncthreads();

    int wwid = tid >> 5, lane = tid & 31;
    int p = wwid >> 2, ng = wwid & 3;          // p in 0..4, ng in 0..3
    int tx = lane & 7, ty = lane >> 3;         // tx: out octet, ty: node pair (0..3)
    // shared-space 32-bit addresses for asm loads
    uint32_t sU_a = (uint32_t)__cvta_generic_to_shared(sU + p * 2048 + ng * 8 + ty * 2);
    uint32_t sW_a = (uint32_t)__cvta_generic_to_shared(sW + p * 4096 + tx * 8);

    const float4* gsrc[4] = { (const float4*)g_aggG, (const float4*)g_aggA,
                              (const float4*)g_aggS, (const float4*)x };

    for (int tile = blockIdx.x; tile < N_TILES; tile += gridDim.x) {
        int base = tile * 32;
        if (tid < 32) {
            int n = base + tid;
            sCi[tid] = (n < N_NODES) ? 1.0f / fmaxf((float)g_cnt[n], 1.0f) : 0.f;
        }
        __syncthreads();
        // stage inputs transposed: 5 panels x 32 nodes x 16 float4-chunks
        for (int idx = tid; idx < 2560; idx += 640) {
            int a = idx >> 9, rem = idx & 511;
            int nl = rem & 31, kq = rem >> 5;
            int n = base + nl;
            float4 v = make_float4(0.f, 0.f, 0.f, 0.f);
            if (n < N_NODES) {
                if (a < 4) {
                    v = gsrc[a][n * 16 + kq];
                    if (a == 2) {
                        float ci = sCi[nl];
                        v.x *= ci; v.y *= ci; v.z *= ci; v.w *= ci;
                    }
                } else {
                    float4 t1 = gsrc[3][n * 16 + kq];
                    float4 t2 = gsrc[2][n * 16 + kq];
                    v = make_float4(t1.x + t2.x, t1.y + t2.y, t1.z + t2.z, t1.w + t2.w);
                }
            }
            float* dstp = sU + a * 2048 + (kq * 4) * 32 + nl;
            dstp[0]  = v.x; dstp[32] = v.y; dstp[64] = v.z; dstp[96] = v.w;
        }
        __syncthreads();

        unsigned long long acc[2][4];
        #pragma unroll
        for (int r = 0; r < 2; r++)
            #pragma unroll
            for (int c = 0; c < 4; c++) acc[r][c] = 0ull;

        #pragma unroll 8
        for (int k = 0; k < 64; k++) {
            float u0, u1;
            asm("ld.shared.v2.f32 {%0, %1}, [%2];"
                : "=f"(u0), "=f"(u1) : "r"(sU_a + (uint32_t)(k * 32 * 4)));
            unsigned long long w01, w23, w45, w67;
            asm("ld.shared.v2.u64 {%0, %1}, [%2];"
                : "=l"(w01), "=l"(w23) : "r"(sW_a + (uint32_t)(k * 64 * 4)));
            asm("ld.shared.v2.u64 {%0, %1}, [%2];"
                : "=l"(w45), "=l"(w67) : "r"(sW_a + (uint32_t)(k * 64 * 4 + 16)));
            unsigned long long u0d = pack2(u0, u0);
            unsigned long long u1d = pack2(u1, u1);
            acc[0][0] = fma2(u0d, w01, acc[0][0]);
            acc[0][1] = fma2(u0d, w23, acc[0][1]);
            acc[0][2] = fma2(u0d, w45, acc[0][2]);
            acc[0][3] = fma2(u0d, w67, acc[0][3]);
            acc[1][0] = fma2(u1d, w01, acc[1][0]);
            acc[1][1] = fma2(u1d, w23, acc[1][1]);
            acc[1][2] = fma2(u1d, w45, acc[1][2]);
            acc[1][3] = fma2(u1d, w67, acc[1][3]);
        }
        #pragma unroll
        for (int r = 0; r < 2; r++) {
            int nl = ng * 8 + ty * 2 + r;
            uint32_t pp = (uint32_t)__cvta_generic_to_shared(sP + (p * 32 + nl) * 66 + tx * 8);
            #pragma unroll
            for (int c = 0; c < 4; c++)
                asm volatile("st.shared.u64 [%0], %1;" :: "r"(pp + 8u * c), "l"(acc[r][c]));
        }
        __syncthreads();

        if (tid < 256) {
            int nl = tid >> 3, jb = tid & 7;
            float z = 0.f;
            #pragma unroll
            for (int jj = 0; jj < 8; jj++) {
                int j = jb * 8 + jj;
                float vg = sP[(0 * 32 + nl) * 66 + j] + sBia[j];
                float va2 = sP[(1 * 32 + nl) * 66 + j] + sBia[64 + j];
                float vs = sP[(2 * 32 + nl) * 66 + j] + sP[(3 * 32 + nl) * 66 + j] + sBia[128 + j];
                float vi = sP[(4 * 32 + nl) * 66 + j] + sBia[192 + j];
                z += fmaxf(vg, 0.f) * sWo[j] + fmaxf(va2, 0.f) * sWo[64 + j]
                   + fmaxf(vs, 0.f) * sWo[128 + j] + fmaxf(vi, 0.f) * sWo[192 + j];
            }
            z += __shfl_down_sync(0xffffffffu, z, 4);
            z += __shfl_down_sync(0xffffffffu, z, 2);
            z += __shfl_down_sync(0xffffffffu, z, 1);
            if ((tid & 7) == 0 && base + nl < N_NODES)
                out[base + nl] = 1.0f / (1.0f + expf(-(z + bout)));
        }
        __syncthreads();
    }
}

// ---------------- launch ----------------
extern "C" void kernel_launch(void* const* d_in, const int* in_sizes, int n_in,
                              void* d_out, int out_size) {
    const float* x    = (const float*)d_in[0];
    const void*  ei   = d_in[1];
    const float* Wg   = (const float*)d_in[2];
    const float* bg   = (const float*)d_in[3];
    const float* Wa   = (const float*)d_in[4];
    const float* asrc = (const float*)d_in[5];
    const float* adst = (const float*)d_in[6];
    const float* ba   = (const float*)d_in[7];
    const float* Wl   = (const float*)d_in[8];
    const float* bl   = (const float*)d_in[9];
    const float* Wr   = (const float*)d_in[10];
    const float* Wi   = (const float*)d_in[11];
    const float* bi   = (const float*)d_in[12];
    const float* Wo   = (const float*)d_in[13];
    const float* bo   = (const float*)d_in[14];
    float* out = (float*)d_out;

    cudaFuncSetAttribute(k_final, cudaFuncAttributeMaxDynamicSharedMemorySize, KF_SMEM_BYTES);

    void* cnt_ptr = nullptr;
    cudaGetSymbolAddress(&cnt_ptr, g_cnt);
    cudaMemsetAsync(cnt_ptr, 0, (N_NODES + 1) * sizeof(int), 0);

    k_convert<<<2048, 256>>>(ei, x, Wa, asrc, adst);                       // 0
    k_rowassign<<<(N_NODES + 255) / 256, 256>>>();                         // 1
    k_scatter<<<1024, 256>>>();                                            // 2
    k_agg<<<(N_NODES * 32 + 255) / 256, 256>>>(x);                         // 3 (profiled)
    k_final<<<148, 640, KF_SMEM_BYTES>>>(x, Wg, bg, Wa, ba, Wl, bl, Wr,    // 4
                                         Wi, bi, Wo, bo, out);
}

// round 10
// speedup vs baseline: 1.3595x; 1.3595x over previous
#include <cuda_runtime.h>
#include <cstdint>

#define N_NODES 50000
#define N_EDGES 800000
#define FDIM 64
#define N_TILES ((N_NODES + 31) / 32)   // 1563
#define XW_BLOCKS 296

// ---------------- device scratch ----------------
__device__ int   g_src[N_EDGES];
__device__ int   g_dst[N_EDGES];
__device__ int   g_csrc[N_EDGES];          // CSR: src ids grouped by dst
__device__ int   g_row[N_NODES];           // CSR slice start per dst (arbitrary order)
__device__ int   g_cnt[N_NODES + 1];       // in-degree histogram; [N] = global offset counter
__device__ int   g_cur[N_NODES];           // scatter cursors
__device__ __align__(16) float g_aggG[N_NODES * FDIM];
__device__ __align__(16) float g_aggA[N_NODES * FDIM];
__device__ __align__(16) float g_aggS[N_NODES * FDIM];
__device__ __align__(16) float g_xw[N_NODES * 128];   // [n][0..63]=x@Wr, [64..127]=x@Wi
__device__ float g_ssrc[N_NODES];
__device__ float g_sdst[N_NODES];
__device__ float g_dinv[N_NODES];

__device__ __forceinline__ float lrelu(float v) { return v > 0.f ? v : 0.2f * v; }

// ---------------- 0: dtype-detect + convert + histogram + per-node attn scalars ----------------
// int64 detection: ids < 50000 so high 32-bit words are 0; if int32, the odd
// words are 64 random ids (all-zero prob ~ (1/50000)^64 ~ 0).
__global__ void k_convert(const void* __restrict__ ei, const float* __restrict__ x,
                          const float* __restrict__ Wa, const float* __restrict__ as_,
                          const float* __restrict__ ad_) {
    __shared__ int s_is64;
    __shared__ float sva[FDIM], svb[FDIM];
    const unsigned int* w = (const unsigned int*)ei;
    int gid = blockIdx.x * blockDim.x + threadIdx.x;

    if (threadIdx.x == 0) {
        int z = 1;
        for (int i = 0; i < 64; i++) if (w[2 * i + 1] != 0u) { z = 0; break; }
        s_is64 = z;
    }
    if (blockIdx.x * blockDim.x < N_NODES) {
        if (threadIdx.x < FDIM) {
            int k = threadIdx.x;
            float va = 0.f, vb = 0.f;
            #pragma unroll 8
            for (int j = 0; j < FDIM; j++) {
                float wv = Wa[k * FDIM + j];
                va = fmaf(wv, as_[j], va);
                vb = fmaf(wv, ad_[j], vb);
            }
            sva[k] = va;
            svb[k] = vb;
        }
        __syncthreads();
        if (gid < N_NODES) {
            const float4* xr = (const float4*)(x + (size_t)gid * FDIM);
            float ss = 0.f, sd = 0.f;
            #pragma unroll
            for (int i = 0; i < FDIM / 4; i++) {
                float4 v = xr[i];
                ss = fmaf(v.x, sva[4*i], fmaf(v.y, sva[4*i+1], fmaf(v.z, sva[4*i+2], fmaf(v.w, sva[4*i+3], ss))));
                sd = fmaf(v.x, svb[4*i], fmaf(v.y, svb[4*i+1], fmaf(v.z, svb[4*i+2], fmaf(v.w, svb[4*i+3], sd))));
            }
            g_ssrc[gid] = ss;
            g_sdst[gid] = sd;
        }
    } else {
        __syncthreads();
    }
    int is64 = s_is64;
    int stride = gridDim.x * blockDim.x;
    for (int i = gid; i < 2 * N_EDGES; i += stride) {
        int v;
        if (is64) v = (int)((const long long*)ei)[i];
        else      v = ((const int*)ei)[i];
        if (i < N_EDGES) g_src[i] = v;
        else {
            g_dst[i - N_EDGES] = v;
            atomicAdd(&g_cnt[v], 1);
        }
    }
}

// ---------------- 1: row-slice assignment (block scan + 1 atomic per block) ----------------
__global__ void k_rowassign() {
    __shared__ int s_warp[8];
    __shared__ int s_base;
    int tid = threadIdx.x;
    int n = blockIdx.x * 256 + tid;
    int lane = tid & 31, wid = tid >> 5;
    int c = (n < N_NODES) ? g_cnt[n] : 0;
    int v = c;
    #pragma unroll
    for (int off = 1; off < 32; off <<= 1) {
        int u = __shfl_up_sync(0xffffffffu, v, off);
        if (lane >= off) v += u;
    }
    if (lane == 31) s_warp[wid] = v;
    __syncthreads();
    if (tid < 8) {
        int pv = s_warp[tid];
        #pragma unroll
        for (int off = 1; off < 8; off <<= 1) {
            int u = __shfl_up_sync(0xffu, pv, off);
            if (tid >= off) pv += u;
        }
        s_warp[tid] = pv;
        if (tid == 7) s_base = atomicAdd(&g_cnt[N_NODES], pv);
    }
    __syncthreads();
    int excl = v - c + (wid > 0 ? s_warp[wid - 1] : 0);
    if (n < N_NODES) {
        g_row[n] = s_base + excl;
        g_cur[n] = 0;
        g_dinv[n] = rsqrtf((float)c + 1.0f);
    }
}

// ---------------- 2: scatter src into CSR ----------------
__global__ void k_scatter() {
    int stride = gridDim.x * blockDim.x;
    for (int e = blockIdx.x * blockDim.x + threadIdx.x; e < N_EDGES; e += stride) {
        int d = g_dst[e];
        int pos = g_row[d] + atomicAdd(&g_cur[d], 1);
        g_csrc[pos] = g_src[e];
    }
}

// ---------------- 3: FAT kernel — xw GEMM blocks + agg blocks (overlap) ----------------
// blocks [0, XW_BLOCKS): XW = x @ [Wr | Wi]   (FMA-bound; fills agg's idle issue slots)
// blocks [XW_BLOCKS, +6250): R5 warp-per-node aggregation (latency-bound, unchanged)
#define AGGXW_SMEM_BYTES ((8192 + 2048) * 4)

__global__ void __launch_bounds__(256) k_agg_xw(const float* __restrict__ x,
                                                const float* __restrict__ Wr,
                                                const float* __restrict__ Wi) {
    extern __shared__ float sx[];
    if (blockIdx.x < XW_BLOCKS) {
        float* sW2 = sx;           // [64][128]: [k][j<64]=Wr[k][j], [k][64+j]=Wi[k][j]
        float* sU  = sx + 8192;    // [64][32] x transposed
        int tid = threadIdx.x;
        for (int i = tid; i < 4096; i += 256) {
            int k = i >> 6, j = i & 63;
            sW2[k * 128 + j]      = Wr[i];
            sW2[k * 128 + 64 + j] = Wi[i];
        }
        __syncthreads();
        int tx = tid & 31, ng = tid >> 5;
        for (int tile = blockIdx.x; tile < N_TILES; tile += XW_BLOCKS) {
            int base = tile * 32;
            for (int idx = tid; idx < 512; idx += 256) {
                int nl = idx & 31, kq = idx >> 5;
                int n = base + nl;
                float4 v = make_float4(0.f, 0.f, 0.f, 0.f);
                if (n < N_NODES) v = ((const float4*)x)[n * 16 + kq];
                float* dstp = sU + (kq * 4) * 32 + nl;
                dstp[0] = v.x; dstp[32] = v.y; dstp[64] = v.z; dstp[96] = v.w;
            }
            __syncthreads();
            float acc[4][4];
            #pragma unroll
            for (int r = 0; r < 4; r++)
                #pragma unroll
                for (int c = 0; c < 4; c++) acc[r][c] = 0.f;
            #pragma unroll 8
            for (int k = 0; k < 64; k++) {
                float4 wv = *(const float4*)(sW2 + k * 128 + tx * 4);
                const float* ub = sU + k * 32 + ng * 4;
                float u0 = ub[0], u1 = ub[1], u2 = ub[2], u3 = ub[3];
                acc[0][0] = fmaf(u0, wv.x, acc[0][0]); acc[0][1] = fmaf(u0, wv.y, acc[0][1]);
                acc[0][2] = fmaf(u0, wv.z, acc[0][2]); acc[0][3] = fmaf(u0, wv.w, acc[0][3]);
                acc[1][0] = fmaf(u1, wv.x, acc[1][0]); acc[1][1] = fmaf(u1, wv.y, acc[1][1]);
                acc[1][2] = fmaf(u1, wv.z, acc[1][2]); acc[1][3] = fmaf(u1, wv.w, acc[1][3]);
                acc[2][0] = fmaf(u2, wv.x, acc[2][0]); acc[2][1] = fmaf(u2, wv.y, acc[2][1]);
                acc[2][2] = fmaf(u2, wv.z, acc[2][2]); acc[2][3] = fmaf(u2, wv.w, acc[2][3]);
                acc[3][0] = fmaf(u3, wv.x, acc[3][0]); acc[3][1] = fmaf(u3, wv.y, acc[3][1]);
                acc[3][2] = fmaf(u3, wv.z, acc[3][2]); acc[3][3] = fmaf(u3, wv.w, acc[3][3]);
            }
            #pragma unroll
            for (int r = 0; r < 4; r++) {
                int n = base + ng * 4 + r;
                if (n < N_NODES)
                    ((float4*)g_xw)[n * 32 + tx] =
                        make_float4(acc[r][0], acc[r][1], acc[r][2], acc[r][3]);
            }
            __syncthreads();
        }
        return;
    }

    // ---- agg path (R5, verbatim logic) ----
    int wid = ((blockIdx.x - XW_BLOCKS) * blockDim.x + threadIdx.x) >> 5;
    int lane = threadIdx.x & 31;
    if (wid >= N_NODES) return;
    int d = wid;
    int row = g_row[d], end = row + g_cnt[d];
    float sd = g_sdst[d];
    float dvd = g_dinv[d];
    int q = lane & 15, half = lane >> 4;

    float4 aG = make_float4(0.f, 0.f, 0.f, 0.f);
    float4 aA = aG, aS = aG;
    float denom = 0.f;

    for (int base = row; base < end; base += 32) {
        int m = min(32, end - base);
        int   s_r = 0;
        float we_r = 0.f, wg_r = 0.f;
        if (lane < m) {
            s_r = g_csrc[base + lane];
            we_r = expf(lrelu(g_ssrc[s_r] + sd));
            wg_r = g_dinv[s_r] * dvd;
            denom += we_r;
        }
        for (int i2 = 0; i2 < m; i2 += 2) {
            int i = i2 + half;
            int ic = (i < m) ? i : 0;
            int   s  = __shfl_sync(0xffffffffu, s_r, ic);
            float we = __shfl_sync(0xffffffffu, we_r, ic);
            float wg = __shfl_sync(0xffffffffu, wg_r, ic);
            if (i < m) {
                float4 xv = ((const float4*)x)[s * 16 + q];
                aG.x = fmaf(wg, xv.x, aG.x); aG.y = fmaf(wg, xv.y, aG.y);
                aG.z = fmaf(wg, xv.z, aG.z); aG.w = fmaf(wg, xv.w, aG.w);
                aA.x = fmaf(we, xv.x, aA.x); aA.y = fmaf(we, xv.y, aA.y);
                aA.z = fmaf(we, xv.z, aA.z); aA.w = fmaf(we, xv.w, aA.w);
                aS.x += xv.x; aS.y += xv.y; aS.z += xv.z; aS.w += xv.w;
            }
        }
    }

    #pragma unroll
    for (int off = 16; off > 0; off >>= 1)
        denom += __shfl_xor_sync(0xffffffffu, denom, off);
    float selfexp = expf(lrelu(g_ssrc[d] + sd));
    float rdenom = 1.0f / (denom + selfexp);

    #pragma unroll
    for (int c = 0; c < 12; c++) {
        float* p = (c < 4) ? (&aG.x + c) : (c < 8) ? (&aA.x + (c - 4)) : (&aS.x + (c - 8));
        *p += __shfl_xor_sync(0xffffffffu, *p, 16);
    }
    if (half == 0) {
        float4 xd = ((const float4*)x)[d * 16 + q];
        float wd = dvd * dvd;
        float4 G = make_float4(fmaf(wd, xd.x, aG.x), fmaf(wd, xd.y, aG.y),
                               fmaf(wd, xd.z, aG.z), fmaf(wd, xd.w, aG.w));
        float4 A = make_float4((aA.x + selfexp * xd.x) * rdenom, (aA.y + selfexp * xd.y) * rdenom,
                               (aA.z + selfexp * xd.z) * rdenom, (aA.w + selfexp * xd.w) * rdenom);
        ((float4*)g_aggG)[d * 16 + q] = G;
        ((float4*)g_aggA)[d * 16 + q] = A;
        ((float4*)g_aggS)[d * 16 + q] = aS;
    }
}

// ---------------- 4: 4-panel GEMM (R5 structure) + xw epilogue ----------------
// panels: 0: aggG@Wg  1: aggA@Wa  2: aggS@Wl (ci applied in epilogue)  3: aggS@Wi
// smem float layout (sU/sP overlaid — sP written only after all sU reads):
//   sW   [4][64][64]  @ 0       (16384)
//   sWo  [4][64]      @ 16384   (256)
//   sBia [4][64]      @ 16640   (256)
//   sCi  [32]         @ 16896   (32)
//   union @ 16928: sU [3][64][32] (6144)  /  sP [4][32][65] (8320)
#define KF_SMEM_FLOATS (16928 + 8320)
#define KF_SMEM_BYTES (KF_SMEM_FLOATS * 4)

__global__ void __launch_bounds__(256, 2) k_final(
        const float* __restrict__ x,
        const float* __restrict__ Wg, const float* __restrict__ bg,
        const float* __restrict__ Wa, const float* __restrict__ ba,
        const float* __restrict__ Wl, const float* __restrict__ bl,
        const float* __restrict__ Wi, const float* __restrict__ bi,
        const float* __restrict__ Wo, const float* __restrict__ bo,
        float* __restrict__ out) {
    extern __shared__ float sm[];
    float* sW   = sm;
    float* sWo  = sm + 16384;
    float* sBia = sm + 16640;
    float* sCi  = sm + 16896;
    float* sU   = sm + 16928;
    float* sP   = sm + 16928;
    int tid = threadIdx.x;

    for (int i = tid; i < 4096; i += 256) {
        sW[i]            = Wg[i];
        sW[4096 + i]     = Wa[i];
        sW[2 * 4096 + i] = Wl[i];
        sW[3 * 4096 + i] = Wi[i];
    }
    if (tid < 256) sWo[tid] = Wo[tid];
    if (tid < 64) {
        sBia[tid] = bg[tid]; sBia[64 + tid] = ba[tid];
        sBia[128 + tid] = bl[tid]; sBia[192 + tid] = bi[tid];
    }
    float bout = bo[0];
    __syncthreads();

    int wwid = tid >> 5, lane = tid & 31;
    int p = wwid >> 1, ng = wwid & 1;          // p in 0..3
    int tx = lane & 15, ty = lane >> 4;
    int ain = (p <= 1) ? p : 2;                // panels 2,3 share aggS input
    const float* Wp = sW + p * 4096;
    const float* Ub = sU + ain * 2048 + ng * 16 + ty * 8;

    const float4* gsrc[3] = { (const float4*)g_aggG, (const float4*)g_aggA,
                              (const float4*)g_aggS };

    for (int tile = blockIdx.x; tile < N_TILES; tile += gridDim.x) {
        int base = tile * 32;
        if (tid < 32) {
            int n = base + tid;
            sCi[tid] = (n < N_NODES) ? 1.0f / fmaxf((float)g_cnt[n], 1.0f) : 0.f;
        }
        __syncthreads();                       // sP of previous tile fully read
        // stage inputs transposed: 3 arrays x 32 nodes x 16 float4-chunks
        for (int idx = tid; idx < 1536; idx += 256) {
            int a = idx / 512, rem = idx & 511;
            int nl = rem & 31, kq = rem >> 5;
            int n = base + nl;
            float4 v = make_float4(0.f, 0.f, 0.f, 0.f);
            if (n < N_NODES) v = gsrc[a][n * 16 + kq];
            float* dstp = sU + a * 2048 + (kq * 4) * 32 + nl;
            dstp[0] = v.x; dstp[32] = v.y; dstp[64] = v.z; dstp[96] = v.w;
        }
        __syncthreads();

        float acc[8][4];
        #pragma unroll
        for (int r = 0; r < 8; r++)
            #pragma unroll
            for (int jj = 0; jj < 4; jj++) acc[r][jj] = 0.f;

        #pragma unroll 4
        for (int k = 0; k < 64; k++) {
            float4 u0 = *(const float4*)(Ub + k * 32);
            float4 u1 = *(const float4*)(Ub + k * 32 + 4);
            float4 wv = *(const float4*)(Wp + k * 64 + tx * 4);
            float ur[8] = {u0.x, u0.y, u0.z, u0.w, u1.x, u1.y, u1.z, u1.w};
            #pragma unroll
            for (int r = 0; r < 8; r++) {
                acc[r][0] = fmaf(ur[r], wv.x, acc[r][0]);
                acc[r][1] = fmaf(ur[r], wv.y, acc[r][1]);
                acc[r][2] = fmaf(ur[r], wv.z, acc[r][2]);
                acc[r][3] = fmaf(ur[r], wv.w, acc[r][3]);
            }
        }
        __syncthreads();                       // all sU reads done before sP overwrite
        #pragma unroll
        for (int r = 0; r < 8; r++) {
            int nl = ng * 16 + ty * 8 + r;
            float* pp = sP + (p * 32 + nl) * 65 + tx * 4;
            pp[0] = acc[r][0]; pp[1] = acc[r][1]; pp[2] = acc[r][2]; pp[3] = acc[r][3];
        }
        __syncthreads();

        {
            int nl = tid >> 3, jb = tid & 7;
            int n = base + nl;
            float ci = sCi[nl];
            const float* xwr = g_xw + (size_t)min(n, N_NODES - 1) * 128 + jb * 8;
            float z = 0.f;
            #pragma unroll
            for (int jj = 0; jj < 8; jj++) {
                int j = jb * 8 + jj;
                float vg = sP[(0 * 32 + nl) * 65 + j] + sBia[j];
                float va2 = sP[(1 * 32 + nl) * 65 + j] + sBia[64 + j];
                float vs = fmaf(ci, sP[(2 * 32 + nl) * 65 + j], xwr[jj]) + sBia[128 + j];
                float vi = sP[(3 * 32 + nl) * 65 + j] + xwr[64 + jj] + sBia[192 + j];
                z += fmaxf(vg, 0.f) * sWo[j] + fmaxf(va2, 0.f) * sWo[64 + j]
                   + fmaxf(vs, 0.f) * sWo[128 + j] + fmaxf(vi, 0.f) * sWo[192 + j];
            }
            z += __shfl_down_sync(0xffffffffu, z, 4);
            z += __shfl_down_sync(0xffffffffu, z, 2);
            z += __shfl_down_sync(0xffffffffu, z, 1);
            if ((tid & 7) == 0 && n < N_NODES)
                out[n] = 1.0f / (1.0f + expf(-(z + bout)));
        }
        __syncthreads();
    }
}

// ---------------- launch ----------------
extern "C" void kernel_launch(void* const* d_in, const int* in_sizes, int n_in,
                              void* d_out, int out_size) {
    const float* x    = (const float*)d_in[0];
    const void*  ei   = d_in[1];
    const float* Wg   = (const float*)d_in[2];
    const float* bg   = (const float*)d_in[3];
    const float* Wa   = (const float*)d_in[4];
    const float* asrc = (const float*)d_in[5];
    const float* adst = (const float*)d_in[6];
    const float* ba   = (const float*)d_in[7];
    const float* Wl   = (const float*)d_in[8];
    const float* bl   = (const float*)d_in[9];
    const float* Wr   = (const float*)d_in[10];
    const float* Wi   = (const float*)d_in[11];
    const float* bi   = (const float*)d_in[12];
    const float* Wo   = (const float*)d_in[13];
    const float* bo   = (const float*)d_in[14];
    float* out = (float*)d_out;

    cudaFuncSetAttribute(k_final, cudaFuncAttributeMaxDynamicSharedMemorySize, KF_SMEM_BYTES);

    void* cnt_ptr = nullptr;
    cudaGetSymbolAddress(&cnt_ptr, g_cnt);
    cudaMemsetAsync(cnt_ptr, 0, (N_NODES + 1) * sizeof(int), 0);

    k_convert<<<2048, 256>>>(ei, x, Wa, asrc, adst);                       // 0
    k_rowassign<<<(N_NODES + 255) / 256, 256>>>();                         // 1
    k_scatter<<<1024, 256>>>();                                            // 2
    k_agg_xw<<<XW_BLOCKS + (N_NODES + 7) / 8, 256, AGGXW_SMEM_BYTES>>>(    // 3 (profiled)
        x, Wr, Wi);
    k_final<<<296, 256, KF_SMEM_BYTES>>>(x, Wg, bg, Wa, ba, Wl, bl,        // 4
                                         Wi, bi, Wo, bo, out);
}

// round 11
// speedup vs baseline: 1.3895x; 1.0221x over previous
#include <cuda_runtime.h>
#include <cstdint>

#define N_NODES 50000
#define N_EDGES 800000
#define FDIM 64
#define N_TILES ((N_NODES + 31) / 32)   // 1563
#define XW_BLOCKS 296
#define CV_BLOCKS 2048

// ---------------- device scratch ----------------
__device__ int   g_src[N_EDGES];
__device__ int   g_dst[N_EDGES];
__device__ int   g_csrc[N_EDGES];          // CSR: src ids grouped by dst
__device__ int   g_row[N_NODES];           // CSR slice start per dst (arbitrary order)
__device__ int   g_cnt[N_NODES + 1];       // in-degree histogram; [N] = global offset counter
__device__ int   g_cur[N_NODES];           // scatter cursors
__device__ __align__(16) float g_aggG[N_NODES * FDIM];
__device__ __align__(16) float g_aggA[N_NODES * FDIM];
__device__ __align__(16) float g_aggS[N_NODES * FDIM];
__device__ __align__(16) float g_xw[N_NODES * 128];   // [n][0..63]=x@Wr, [64..127]=x@Wi
__device__ float g_ssrc[N_NODES];
__device__ float g_sdst[N_NODES];
__device__ float g_dinv[N_NODES];

__device__ __forceinline__ float lrelu(float v) { return v > 0.f ? v : 0.2f * v; }

// ---------------- 0: FAT kernel — xw GEMM blocks + convert/histogram blocks ----------------
// blocks [0, XW_BLOCKS): XW = x @ [Wr | Wi]  (FMA-bound)
// blocks [XW_BLOCKS, +CV_BLOCKS): dtype-detect + convert + histogram + attn scalars
//   (DRAM-bound, issue ~5% -> xw FMA fills the idle slots)
#define CVXW_SMEM_BYTES ((8192 + 2048) * 4)

__global__ void __launch_bounds__(256) k_convert_xw(
        const void* __restrict__ ei, const float* __restrict__ x,
        const float* __restrict__ Wa, const float* __restrict__ as_,
        const float* __restrict__ ad_,
        const float* __restrict__ Wr, const float* __restrict__ Wi) {
    extern __shared__ float sx[];
    int tid = threadIdx.x;

    if (blockIdx.x < XW_BLOCKS) {
        // ---- xw GEMM path ----
        float* sW2 = sx;           // [64][128]: [k][j<64]=Wr[k][j], [k][64+j]=Wi[k][j]
        float* sU  = sx + 8192;    // [64][32] x transposed
        for (int i = tid; i < 4096; i += 256) {
            int k = i >> 6, j = i & 63;
            sW2[k * 128 + j]      = Wr[i];
            sW2[k * 128 + 64 + j] = Wi[i];
        }
        __syncthreads();
        int tx = tid & 31, ng = tid >> 5;
        for (int tile = blockIdx.x; tile < N_TILES; tile += XW_BLOCKS) {
            int base = tile * 32;
            for (int idx = tid; idx < 512; idx += 256) {
                int nl = idx & 31, kq = idx >> 5;
                int n = base + nl;
                float4 v = make_float4(0.f, 0.f, 0.f, 0.f);
                if (n < N_NODES) v = ((const float4*)x)[n * 16 + kq];
                float* dstp = sU + (kq * 4) * 32 + nl;
                dstp[0] = v.x; dstp[32] = v.y; dstp[64] = v.z; dstp[96] = v.w;
            }
            __syncthreads();
            float acc[4][4];
            #pragma unroll
            for (int r = 0; r < 4; r++)
                #pragma unroll
                for (int c = 0; c < 4; c++) acc[r][c] = 0.f;
            #pragma unroll 8
            for (int k = 0; k < 64; k++) {
                float4 wv = *(const float4*)(sW2 + k * 128 + tx * 4);
                float4 uv = *(const float4*)(sU + k * 32 + ng * 4);
                acc[0][0] = fmaf(uv.x, wv.x, acc[0][0]); acc[0][1] = fmaf(uv.x, wv.y, acc[0][1]);
                acc[0][2] = fmaf(uv.x, wv.z, acc[0][2]); acc[0][3] = fmaf(uv.x, wv.w, acc[0][3]);
                acc[1][0] = fmaf(uv.y, wv.x, acc[1][0]); acc[1][1] = fmaf(uv.y, wv.y, acc[1][1]);
                acc[1][2] = fmaf(uv.y, wv.z, acc[1][2]); acc[1][3] = fmaf(uv.y, wv.w, acc[1][3]);
                acc[2][0] = fmaf(uv.z, wv.x, acc[2][0]); acc[2][1] = fmaf(uv.z, wv.y, acc[2][1]);
                acc[2][2] = fmaf(uv.z, wv.z, acc[2][2]); acc[2][3] = fmaf(uv.z, wv.w, acc[2][3]);
                acc[3][0] = fmaf(uv.w, wv.x, acc[3][0]); acc[3][1] = fmaf(uv.w, wv.y, acc[3][1]);
                acc[3][2] = fmaf(uv.w, wv.z, acc[3][2]); acc[3][3] = fmaf(uv.w, wv.w, acc[3][3]);
            }
            #pragma unroll
            for (int r = 0; r < 4; r++) {
                int n = base + ng * 4 + r;
                if (n < N_NODES)
                    ((float4*)g_xw)[n * 32 + tx] =
                        make_float4(acc[r][0], acc[r][1], acc[r][2], acc[r][3]);
            }
            __syncthreads();
        }
        return;
    }

    // ---- convert path ----
    int bb = blockIdx.x - XW_BLOCKS;
    float* sva = sx;                 // [64]
    float* svb = sx + 64;            // [64]
    int*   s_is64p = (int*)(sx + 128);
    const unsigned int* w = (const unsigned int*)ei;
    int gid = bb * 256 + tid;

    if (tid == 0) {
        // int64 detection: ids < 50000 so high 32-bit words are 0; if int32, the
        // odd words are 64 random ids (all-zero prob ~ (1/50000)^64 ~ 0).
        int z = 1;
        for (int i = 0; i < 64; i++) if (w[2 * i + 1] != 0u) { z = 0; break; }
        *s_is64p = z;
    }
    if (bb * 256 < N_NODES) {
        if (tid < FDIM) {
            int k = tid;
            float va = 0.f, vb = 0.f;
            #pragma unroll 8
            for (int j = 0; j < FDIM; j++) {
                float wv = Wa[k * FDIM + j];
                va = fmaf(wv, as_[j], va);
                vb = fmaf(wv, ad_[j], vb);
            }
            sva[k] = va;
            svb[k] = vb;
        }
        __syncthreads();
        if (gid < N_NODES) {
            const float4* xr = (const float4*)(x + (size_t)gid * FDIM);
            float ss = 0.f, sd = 0.f;
            #pragma unroll
            for (int i = 0; i < FDIM / 4; i++) {
                float4 v = xr[i];
                ss = fmaf(v.x, sva[4*i], fmaf(v.y, sva[4*i+1], fmaf(v.z, sva[4*i+2], fmaf(v.w, sva[4*i+3], ss))));
                sd = fmaf(v.x, svb[4*i], fmaf(v.y, svb[4*i+1], fmaf(v.z, svb[4*i+2], fmaf(v.w, svb[4*i+3], sd))));
            }
            g_ssrc[gid] = ss;
            g_sdst[gid] = sd;
        }
    } else {
        __syncthreads();
    }
    int is64 = *s_is64p;
    int stride = CV_BLOCKS * 256;
    for (int i = gid; i < 2 * N_EDGES; i += stride) {
        int v;
        if (is64) v = (int)((const long long*)ei)[i];
        else      v = ((const int*)ei)[i];
        if (i < N_EDGES) g_src[i] = v;
        else {
            g_dst[i - N_EDGES] = v;
            atomicAdd(&g_cnt[v], 1);
        }
    }
}

// ---------------- 1: row-slice assignment (block scan + 1 atomic per block) ----------------
__global__ void k_rowassign() {
    __shared__ int s_warp[8];
    __shared__ int s_base;
    int tid = threadIdx.x;
    int n = blockIdx.x * 256 + tid;
    int lane = tid & 31, wid = tid >> 5;
    int c = (n < N_NODES) ? g_cnt[n] : 0;
    int v = c;
    #pragma unroll
    for (int off = 1; off < 32; off <<= 1) {
        int u = __shfl_up_sync(0xffffffffu, v, off);
        if (lane >= off) v += u;
    }
    if (lane == 31) s_warp[wid] = v;
    __syncthreads();
    if (tid < 8) {
        int pv = s_warp[tid];
        #pragma unroll
        for (int off = 1; off < 8; off <<= 1) {
            int u = __shfl_up_sync(0xffu, pv, off);
            if (tid >= off) pv += u;
        }
        s_warp[tid] = pv;
        if (tid == 7) s_base = atomicAdd(&g_cnt[N_NODES], pv);
    }
    __syncthreads();
    int excl = v - c + (wid > 0 ? s_warp[wid - 1] : 0);
    if (n < N_NODES) {
        g_row[n] = s_base + excl;
        g_cur[n] = 0;
        g_dinv[n] = rsqrtf((float)c + 1.0f);
    }
}

// ---------------- 2: scatter src into CSR ----------------
__global__ void k_scatter() {
    int stride = gridDim.x * blockDim.x;
    for (int e = blockIdx.x * blockDim.x + threadIdx.x; e < N_EDGES; e += stride) {
        int d = g_dst[e];
        int pos = g_row[d] + atomicAdd(&g_cur[d], 1);
        g_csrc[pos] = g_src[e];
    }
}

// ---------------- 3: warp-per-node aggregation — shfl path, unrolled x2 (MLP 2) ----------------
__global__ void __launch_bounds__(256) k_agg(const float* __restrict__ x) {
    int wid = (blockIdx.x * blockDim.x + threadIdx.x) >> 5;
    int lane = threadIdx.x & 31;
    if (wid >= N_NODES) return;
    int d = wid;
    int row = g_row[d], end = row + g_cnt[d];
    float sd = g_sdst[d];
    float dvd = g_dinv[d];
    int q = lane & 15, half = lane >> 4;
    const float4* x4 = (const float4*)x;

    float4 aG = make_float4(0.f, 0.f, 0.f, 0.f);
    float4 aA = aG, aS = aG;
    float denom = 0.f;

    for (int base = row; base < end; base += 32) {
        int m = min(32, end - base);
        int   s_r = 0;
        float we_r = 0.f, wg_r = 0.f;
        if (lane < m) {
            s_r = g_csrc[base + lane];
            we_r = expf(lrelu(g_ssrc[s_r] + sd));
            wg_r = g_dinv[s_r] * dvd;
            denom += we_r;
        }
        int mm = m & ~3;
        for (int i2 = 0; i2 < mm; i2 += 4) {
            int   sA  = __shfl_sync(0xffffffffu, s_r,  i2 + half);
            float weA = __shfl_sync(0xffffffffu, we_r, i2 + half);
            float wgA = __shfl_sync(0xffffffffu, wg_r, i2 + half);
            int   sB  = __shfl_sync(0xffffffffu, s_r,  i2 + 2 + half);
            float weB = __shfl_sync(0xffffffffu, we_r, i2 + 2 + half);
            float wgB = __shfl_sync(0xffffffffu, wg_r, i2 + 2 + half);
            float4 xvA = x4[sA * 16 + q];     // two independent gathers -> MLP 2
            float4 xvB = x4[sB * 16 + q];
            aG.x = fmaf(wgA, xvA.x, aG.x); aG.y = fmaf(wgA, xvA.y, aG.y);
            aG.z = fmaf(wgA, xvA.z, aG.z); aG.w = fmaf(wgA, xvA.w, aG.w);
            aA.x = fmaf(weA, xvA.x, aA.x); aA.y = fmaf(weA, xvA.y, aA.y);
            aA.z = fmaf(weA, xvA.z, aA.z); aA.w = fmaf(weA, xvA.w, aA.w);
            aS.x += xvA.x; aS.y += xvA.y; aS.z += xvA.z; aS.w += xvA.w;
            aG.x = fmaf(wgB, xvB.x, aG.x); aG.y = fmaf(wgB, xvB.y, aG.y);
            aG.z = fmaf(wgB, xvB.z, aG.z); aG.w = fmaf(wgB, xvB.w, aG.w);
            aA.x = fmaf(weB, xvB.x, aA.x); aA.y = fmaf(weB, xvB.y, aA.y);
            aA.z = fmaf(weB, xvB.z, aA.z); aA.w = fmaf(weB, xvB.w, aA.w);
            aS.x += xvB.x; aS.y += xvB.y; aS.z += xvB.z; aS.w += xvB.w;
        }
        for (int i2 = mm; i2 < m; i2 += 2) {
            int i = i2 + half;
            int ic = (i < m) ? i : 0;
            int   s  = __shfl_sync(0xffffffffu, s_r, ic);
            float we = __shfl_sync(0xffffffffu, we_r, ic);
            float wg = __shfl_sync(0xffffffffu, wg_r, ic);
            if (i < m) {
                float4 xv = x4[s * 16 + q];
                aG.x = fmaf(wg, xv.x, aG.x); aG.y = fmaf(wg, xv.y, aG.y);
                aG.z = fmaf(wg, xv.z, aG.z); aG.w = fmaf(wg, xv.w, aG.w);
                aA.x = fmaf(we, xv.x, aA.x); aA.y = fmaf(we, xv.y, aA.y);
                aA.z = fmaf(we, xv.z, aA.z); aA.w = fmaf(we, xv.w, aA.w);
                aS.x += xv.x; aS.y += xv.y; aS.z += xv.z; aS.w += xv.w;
            }
        }
    }

    #pragma unroll
    for (int off = 16; off > 0; off >>= 1)
        denom += __shfl_xor_sync(0xffffffffu, denom, off);
    float selfexp = expf(lrelu(g_ssrc[d] + sd));
    float rdenom = 1.0f / (denom + selfexp);

    #pragma unroll
    for (int c = 0; c < 12; c++) {
        float* p = (c < 4) ? (&aG.x + c) : (c < 8) ? (&aA.x + (c - 4)) : (&aS.x + (c - 8));
        *p += __shfl_xor_sync(0xffffffffu, *p, 16);
    }
    if (half == 0) {
        float4 xd = x4[d * 16 + q];
        float wd = dvd * dvd;
        float4 G = make_float4(fmaf(wd, xd.x, aG.x), fmaf(wd, xd.y, aG.y),
                               fmaf(wd, xd.z, aG.z), fmaf(wd, xd.w, aG.w));
        float4 A = make_float4((aA.x + selfexp * xd.x) * rdenom, (aA.y + selfexp * xd.y) * rdenom,
                               (aA.z + selfexp * xd.z) * rdenom, (aA.w + selfexp * xd.w) * rdenom);
        ((float4*)g_aggG)[d * 16 + q] = G;
        ((float4*)g_aggA)[d * 16 + q] = A;
        ((float4*)g_aggS)[d * 16 + q] = aS;
    }
}

// ---------------- 4: 4-panel GEMM + xw epilogue (R10, measured) ----------------
// panels: 0: aggG@Wg  1: aggA@Wa  2: aggS@Wl (ci in epilogue)  3: aggS@Wi
// smem float layout (sU/sP overlaid — sP written only after all sU reads):
//   sW   [4][64][64]  @ 0       (16384)
//   sWo  [4][64]      @ 16384   (256)
//   sBia [4][64]      @ 16640   (256)
//   sCi  [32]         @ 16896   (32)
//   union @ 16928: sU [3][64][32] (6144)  /  sP [4][32][65] (8320)
#define KF_SMEM_FLOATS (16928 + 8320)
#define KF_SMEM_BYTES (KF_SMEM_FLOATS * 4)

__global__ void __launch_bounds__(256, 2) k_final(
        const float* __restrict__ x,
        const float* __restrict__ Wg, const float* __restrict__ bg,
        const float* __restrict__ Wa, const float* __restrict__ ba,
        const float* __restrict__ Wl, const float* __restrict__ bl,
        const float* __restrict__ Wi, const float* __restrict__ bi,
        const float* __restrict__ Wo, const float* __restrict__ bo,
        float* __restrict__ out) {
    extern __shared__ float sm[];
    float* sW   = sm;
    float* sWo  = sm + 16384;
    float* sBia = sm + 16640;
    float* sCi  = sm + 16896;
    float* sU   = sm + 16928;
    float* sP   = sm + 16928;
    int tid = threadIdx.x;

    for (int i = tid; i < 4096; i += 256) {
        sW[i]            = Wg[i];
        sW[4096 + i]     = Wa[i];
        sW[2 * 4096 + i] = Wl[i];
        sW[3 * 4096 + i] = Wi[i];
    }
    if (tid < 256) sWo[tid] = Wo[tid];
    if (tid < 64) {
        sBia[tid] = bg[tid]; sBia[64 + tid] = ba[tid];
        sBia[128 + tid] = bl[tid]; sBia[192 + tid] = bi[tid];
    }
    float bout = bo[0];
    __syncthreads();

    int wwid = tid >> 5, lane = tid & 31;
    int p = wwid >> 1, ng = wwid & 1;          // p in 0..3
    int tx = lane & 15, ty = lane >> 4;
    int ain = (p <= 1) ? p : 2;                // panels 2,3 share aggS input
    const float* Wp = sW + p * 4096;
    const float* Ub = sU + ain * 2048 + ng * 16 + ty * 8;

    const float4* gsrc[3] = { (const float4*)g_aggG, (const float4*)g_aggA,
                              (const float4*)g_aggS };

    for (int tile = blockIdx.x; tile < N_TILES; tile += gridDim.x) {
        int base = tile * 32;
        if (tid < 32) {
            int n = base + tid;
            sCi[tid] = (n < N_NODES) ? 1.0f / fmaxf((float)g_cnt[n], 1.0f) : 0.f;
        }
        __syncthreads();                       // sP of previous tile fully read
        for (int idx = tid; idx < 1536; idx += 256) {
            int a = idx / 512, rem = idx & 511;
            int nl = rem & 31, kq = rem >> 5;
            int n = base + nl;
            float4 v = make_float4(0.f, 0.f, 0.f, 0.f);
            if (n < N_NODES) v = gsrc[a][n * 16 + kq];
            float* dstp = sU + a * 2048 + (kq * 4) * 32 + nl;
            dstp[0] = v.x; dstp[32] = v.y; dstp[64] = v.z; dstp[96] = v.w;
        }
        __syncthreads();

        float acc[8][4];
        #pragma unroll
        for (int r = 0; r < 8; r++)
            #pragma unroll
            for (int jj = 0; jj < 4; jj++) acc[r][jj] = 0.f;

        #pragma unroll 4
        for (int k = 0; k < 64; k++) {
            float4 u0 = *(const float4*)(Ub + k * 32);
            float4 u1 = *(const float4*)(Ub + k * 32 + 4);
            float4 wv = *(const float4*)(Wp + k * 64 + tx * 4);
            float ur[8] = {u0.x, u0.y, u0.z, u0.w, u1.x, u1.y, u1.z, u1.w};
            #pragma unroll
            for (int r = 0; r < 8; r++) {
                acc[r][0] = fmaf(ur[r], wv.x, acc[r][0]);
                acc[r][1] = fmaf(ur[r], wv.y, acc[r][1]);
                acc[r][2] = fmaf(ur[r], wv.z, acc[r][2]);
                acc[r][3] = fmaf(ur[r], wv.w, acc[r][3]);
            }
        }
        __syncthreads();                       // all sU reads done before sP overwrite
        #pragma unroll
        for (int r = 0; r < 8; r++) {
            int nl = ng * 16 + ty * 8 + r;
            float* pp = sP + (p * 32 + nl) * 65 + tx * 4;
            pp[0] = acc[r][0]; pp[1] = acc[r][1]; pp[2] = acc[r][2]; pp[3] = acc[r][3];
        }
        __syncthreads();

        {
            int nl = tid >> 3, jb = tid & 7;
            int n = base + nl;
            float ci = sCi[nl];
            const float* xwr = g_xw + (size_t)min(n, N_NODES - 1) * 128 + jb * 8;
            float z = 0.f;
            #pragma unroll
            for (int jj = 0; jj < 8; jj++) {
                int j = jb * 8 + jj;
                float vg = sP[(0 * 32 + nl) * 65 + j] + sBia[j];
                float va2 = sP[(1 * 32 + nl) * 65 + j] + sBia[64 + j];
                float vs = fmaf(ci, sP[(2 * 32 + nl) * 65 + j], xwr[jj]) + sBia[128 + j];
                float vi = sP[(3 * 32 + nl) * 65 + j] + xwr[64 + jj] + sBia[192 + j];
                z += fmaxf(vg, 0.f) * sWo[j] + fmaxf(va2, 0.f) * sWo[64 + j]
                   + fmaxf(vs, 0.f) * sWo[128 + j] + fmaxf(vi, 0.f) * sWo[192 + j];
            }
            z += __shfl_down_sync(0xffffffffu, z, 4);
            z += __shfl_down_sync(0xffffffffu, z, 2);
            z += __shfl_down_sync(0xffffffffu, z, 1);
            if ((tid & 7) == 0 && n < N_NODES)
                out[n] = 1.0f / (1.0f + expf(-(z + bout)));
        }
        __syncthreads();
    }
}

// ---------------- launch ----------------
extern "C" void kernel_launch(void* const* d_in, const int* in_sizes, int n_in,
                              void* d_out, int out_size) {
    const float* x    = (const float*)d_in[0];
    const void*  ei   = d_in[1];
    const float* Wg   = (const float*)d_in[2];
    const float* bg   = (const float*)d_in[3];
    const float* Wa   = (const float*)d_in[4];
    const float* asrc = (const float*)d_in[5];
    const float* adst = (const float*)d_in[6];
    const float* ba   = (const float*)d_in[7];
    const float* Wl   = (const float*)d_in[8];
    const float* bl   = (const float*)d_in[9];
    const float* Wr   = (const float*)d_in[10];
    const float* Wi   = (const float*)d_in[11];
    const float* bi   = (const float*)d_in[12];
    const float* Wo   = (const float*)d_in[13];
    const float* bo   = (const float*)d_in[14];
    float* out = (float*)d_out;

    cudaFuncSetAttribute(k_final, cudaFuncAttributeMaxDynamicSharedMemorySize, KF_SMEM_BYTES);

    void* cnt_ptr = nullptr;
    cudaGetSymbolAddress(&cnt_ptr, g_cnt);
    cudaMemsetAsync(cnt_ptr, 0, (N_NODES + 1) * sizeof(int), 0);

    k_convert_xw<<<XW_BLOCKS + CV_BLOCKS, 256, CVXW_SMEM_BYTES>>>(          // 0
        ei, x, Wa, asrc, adst, Wr, Wi);
    k_rowassign<<<(N_NODES + 255) / 256, 256>>>();                          // 1
    k_scatter<<<1024, 256>>>();                                             // 2
    k_agg<<<(N_NODES * 32 + 255) / 256, 256>>>(x);                          // 3 (profiled)
    k_final<<<296, 256, KF_SMEM_BYTES>>>(x, Wg, bg, Wa, ba, Wl, bl,         // 4
                                         Wi, bi, Wo, bo, out);
}

// round 12
// speedup vs baseline: 1.4248x; 1.0254x over previous
#include <cuda_runtime.h>
#include <cstdint>

#define N_NODES 50000
#define N_EDGES 800000
#define FDIM 64
#define N_TILES ((N_NODES + 31) / 32)   // 1563

// ---------------- device scratch ----------------
__device__ int   g_src[N_EDGES];
__device__ int   g_dst[N_EDGES];
__device__ int   g_csrc[N_EDGES];          // CSR: src ids grouped by dst
__device__ int   g_row[N_NODES];           // CSR slice start per dst (arbitrary order)
__device__ int   g_cnt[N_NODES + 1];       // in-degree histogram; [N] = global offset counter
__device__ int   g_cur[N_NODES];           // scatter cursors
__device__ __align__(16) float g_aggG[N_NODES * FDIM];
__device__ __align__(16) float g_aggA[N_NODES * FDIM];
__device__ __align__(16) float g_aggS[N_NODES * FDIM];
__device__ __align__(8)  float2 g_sd[N_NODES];   // {ssrc, dinv} packed for 1-LDG edge gather
__device__ float g_sdst[N_NODES];
__device__ float g_z1[N_NODES];            // partial head output (GCN+GAT branches)

__device__ __forceinline__ float lrelu(float v) { return v > 0.f ? v : 0.2f * v; }

// ---------------- 0: dtype-detect + convert + histogram + per-node attn scalars ----------------
// int64 detection: ids < 50000 so high 32-bit words are 0; if int32, the odd
// words are 64 random ids (all-zero prob ~ (1/50000)^64 ~ 0).
__global__ void k_convert(const void* __restrict__ ei, const float* __restrict__ x,
                          const float* __restrict__ Wa, const float* __restrict__ as_,
                          const float* __restrict__ ad_) {
    __shared__ int s_is64;
    __shared__ float sva[FDIM], svb[FDIM];
    const unsigned int* w = (const unsigned int*)ei;
    int gid = blockIdx.x * blockDim.x + threadIdx.x;

    if (threadIdx.x == 0) {
        int z = 1;
        for (int i = 0; i < 64; i++) if (w[2 * i + 1] != 0u) { z = 0; break; }
        s_is64 = z;
    }
    if (blockIdx.x * blockDim.x < N_NODES) {
        if (threadIdx.x < FDIM) {
            int k = threadIdx.x;
            float va = 0.f, vb = 0.f;
            #pragma unroll 8
            for (int j = 0; j < FDIM; j++) {
                float wv = Wa[k * FDIM + j];
                va = fmaf(wv, as_[j], va);
                vb = fmaf(wv, ad_[j], vb);
            }
            sva[k] = va;
            svb[k] = vb;
        }
        __syncthreads();
        if (gid < N_NODES) {
            const float4* xr = (const float4*)(x + (size_t)gid * FDIM);
            float ss = 0.f, sd = 0.f;
            #pragma unroll
            for (int i = 0; i < FDIM / 4; i++) {
                float4 v = xr[i];
                ss = fmaf(v.x, sva[4*i], fmaf(v.y, sva[4*i+1], fmaf(v.z, sva[4*i+2], fmaf(v.w, sva[4*i+3], ss))));
                sd = fmaf(v.x, svb[4*i], fmaf(v.y, svb[4*i+1], fmaf(v.z, svb[4*i+2], fmaf(v.w, svb[4*i+3], sd))));
            }
            g_sd[gid].x = ss;
            g_sdst[gid] = sd;
        }
    } else {
        __syncthreads();
    }
    int is64 = s_is64;
    int stride = gridDim.x * blockDim.x;
    for (int i = gid; i < 2 * N_EDGES; i += stride) {
        int v;
        if (is64) v = (int)((const long long*)ei)[i];
        else      v = ((const int*)ei)[i];
        if (i < N_EDGES) g_src[i] = v;
        else {
            g_dst[i - N_EDGES] = v;
            atomicAdd(&g_cnt[v], 1);
        }
    }
}

// ---------------- 1: row-slice assignment (block scan + 1 atomic per block) ----------------
__global__ void k_rowassign() {
    __shared__ int s_warp[8];
    __shared__ int s_base;
    int tid = threadIdx.x;
    int n = blockIdx.x * 256 + tid;
    int lane = tid & 31, wid = tid >> 5;
    int c = (n < N_NODES) ? g_cnt[n] : 0;
    int v = c;
    #pragma unroll
    for (int off = 1; off < 32; off <<= 1) {
        int u = __shfl_up_sync(0xffffffffu, v, off);
        if (lane >= off) v += u;
    }
    if (lane == 31) s_warp[wid] = v;
    __syncthreads();
    if (tid < 8) {
        int pv = s_warp[tid];
        #pragma unroll
        for (int off = 1; off < 8; off <<= 1) {
            int u = __shfl_up_sync(0xffu, pv, off);
            if (tid >= off) pv += u;
        }
        s_warp[tid] = pv;
        if (tid == 7) s_base = atomicAdd(&g_cnt[N_NODES], pv);
    }
    __syncthreads();
    int excl = v - c + (wid > 0 ? s_warp[wid - 1] : 0);
    if (n < N_NODES) {
        g_row[n] = s_base + excl;
        g_cur[n] = 0;
        g_sd[n].y = rsqrtf((float)c + 1.0f);
    }
}

// ---------------- 2: scatter src into CSR ----------------
__global__ void k_scatter() {
    int stride = gridDim.x * blockDim.x;
    for (int e = blockIdx.x * blockDim.x + threadIdx.x; e < N_EDGES; e += stride) {
        int d = g_dst[e];
        int pos = g_row[d] + atomicAdd(&g_cur[d], 1);
        g_csrc[pos] = g_src[e];
    }
}

// ---------------- 3: warp-per-node aggregation (R5 shuffle version + packed float2) ----------------
__global__ void __launch_bounds__(256) k_agg(const float* __restrict__ x) {
    int wid = (blockIdx.x * blockDim.x + threadIdx.x) >> 5;
    int lane = threadIdx.x & 31;
    if (wid >= N_NODES) return;
    int d = wid;
    int row = g_row[d], end = row + g_cnt[d];
    float sd = g_sdst[d];
    float2 dsd = g_sd[d];
    float dvd = dsd.y;
    int q = lane & 15, half = lane >> 4;

    float4 aG = make_float4(0.f, 0.f, 0.f, 0.f);
    float4 aA = aG, aS = aG;
    float denom = 0.f;

    for (int base = row; base < end; base += 32) {
        int m = min(32, end - base);
        int   s_r = 0;
        float we_r = 0.f, wg_r = 0.f;
        if (lane < m) {
            s_r = g_csrc[base + lane];
            float2 sv = g_sd[s_r];              // one 8B gather: {ssrc, dinv}
            we_r = expf(lrelu(sv.x + sd));
            wg_r = sv.y * dvd;
            denom += we_r;
        }
        for (int i2 = 0; i2 < m; i2 += 2) {
            int i = i2 + half;
            int ic = (i < m) ? i : 0;
            int   s  = __shfl_sync(0xffffffffu, s_r, ic);
            float we = __shfl_sync(0xffffffffu, we_r, ic);
            float wg = __shfl_sync(0xffffffffu, wg_r, ic);
            if (i < m) {
                float4 xv = ((const float4*)x)[s * 16 + q];
                aG.x = fmaf(wg, xv.x, aG.x); aG.y = fmaf(wg, xv.y, aG.y);
                aG.z = fmaf(wg, xv.z, aG.z); aG.w = fmaf(wg, xv.w, aG.w);
                aA.x = fmaf(we, xv.x, aA.x); aA.y = fmaf(we, xv.y, aA.y);
                aA.z = fmaf(we, xv.z, aA.z); aA.w = fmaf(we, xv.w, aA.w);
                aS.x += xv.x; aS.y += xv.y; aS.z += xv.z; aS.w += xv.w;
            }
        }
    }

    #pragma unroll
    for (int off = 16; off > 0; off >>= 1)
        denom += __shfl_xor_sync(0xffffffffu, denom, off);
    float selfexp = expf(lrelu(dsd.x + sd));
    float rdenom = 1.0f / (denom + selfexp);

    #pragma unroll
    for (int c = 0; c < 12; c++) {
        float* p = (c < 4) ? (&aG.x + c) : (c < 8) ? (&aA.x + (c - 4)) : (&aS.x + (c - 8));
        *p += __shfl_xor_sync(0xffffffffu, *p, 16);
    }
    if (half == 0) {
        float4 xd = ((const float4*)x)[d * 16 + q];
        float wd = dvd * dvd;
        float4 G = make_float4(fmaf(wd, xd.x, aG.x), fmaf(wd, xd.y, aG.y),
                               fmaf(wd, xd.z, aG.z), fmaf(wd, xd.w, aG.w));
        float4 A = make_float4((aA.x + selfexp * xd.x) * rdenom, (aA.y + selfexp * xd.y) * rdenom,
                               (aA.z + selfexp * xd.z) * rdenom, (aA.w + selfexp * xd.w) * rdenom);
        ((float4*)g_aggG)[d * 16 + q] = G;
        ((float4*)g_aggA)[d * 16 + q] = A;
        ((float4*)g_aggS)[d * 16 + q] = aS;
    }
}

// ---------------- 4: kF1 — panels {aggG@Wg, aggA@Wa} -> partial head z1 ----------------
// 256 thr = 8 warps = 2 panels x 4 node-groups(8). 50.4KB smem -> 4 blocks/SM.
// smem: sW[2][4096] @0, sWo[2][64] @8192, sBia[2][64] @8320, union @8448: sU[2][64][32] / sP[2][32][65]
#define KF1_SMEM_FLOATS (8448 + 4160)
#define KF1_SMEM_BYTES (KF1_SMEM_FLOATS * 4)

__global__ void __launch_bounds__(256, 4) k_final1(
        const float* __restrict__ Wg, const float* __restrict__ bg,
        const float* __restrict__ Wa, const float* __restrict__ ba,
        const float* __restrict__ Wo) {
    extern __shared__ float sm[];
    float* sW   = sm;
    float* sWo  = sm + 8192;
    float* sBia = sm + 8320;
    float* sU   = sm + 8448;
    float* sP   = sm + 8448;
    int tid = threadIdx.x;

    for (int i = tid; i < 4096; i += 256) {
        sW[i]        = Wg[i];
        sW[4096 + i] = Wa[i];
    }
    if (tid < 128) sWo[tid] = Wo[tid];          // WoG | WoA
    if (tid < 64) { sBia[tid] = bg[tid]; sBia[64 + tid] = ba[tid]; }
    __syncthreads();

    int wwid = tid >> 5, lane = tid & 31;
    int p = wwid >> 2, ng = wwid & 3;           // p in 0..1, ng in 0..3
    int tx = lane & 15, ty = lane >> 4;
    const float* Wp = sW + p * 4096;
    const float* Ub = sU + p * 2048 + ng * 8 + ty * 4;

    const float4* gsrc[2] = { (const float4*)g_aggG, (const float4*)g_aggA };

    for (int tile = blockIdx.x; tile < N_TILES; tile += gridDim.x) {
        int base = tile * 32;
        __syncthreads();                        // previous tile's sP fully read
        for (int idx = tid; idx < 1024; idx += 256) {
            int a = idx >> 9, rem = idx & 511;
            int nl = rem & 31, kq = rem >> 5;
            int n = base + nl;
            float4 v = make_float4(0.f, 0.f, 0.f, 0.f);
            if (n < N_NODES) v = gsrc[a][n * 16 + kq];
            float* dstp = sU + a * 2048 + (kq * 4) * 32 + nl;
            dstp[0] = v.x; dstp[32] = v.y; dstp[64] = v.z; dstp[96] = v.w;
        }
        __syncthreads();

        float acc[4][4];
        #pragma unroll
        for (int r = 0; r < 4; r++)
            #pragma unroll
            for (int c = 0; c < 4; c++) acc[r][c] = 0.f;

        #pragma unroll 8
        for (int k = 0; k < 64; k++) {
            float4 u = *(const float4*)(Ub + k * 32);
            float4 wv = *(const float4*)(Wp + k * 64 + tx * 4);
            float ur[4] = {u.x, u.y, u.z, u.w};
            #pragma unroll
            for (int r = 0; r < 4; r++) {
                acc[r][0] = fmaf(ur[r], wv.x, acc[r][0]);
                acc[r][1] = fmaf(ur[r], wv.y, acc[r][1]);
                acc[r][2] = fmaf(ur[r], wv.z, acc[r][2]);
                acc[r][3] = fmaf(ur[r], wv.w, acc[r][3]);
            }
        }
        __syncthreads();                        // sU reads done before sP overwrite
        #pragma unroll
        for (int r = 0; r < 4; r++) {
            int nl = ng * 8 + ty * 4 + r;
            float* pp = sP + (p * 32 + nl) * 65 + tx * 4;
            pp[0] = acc[r][0]; pp[1] = acc[r][1]; pp[2] = acc[r][2]; pp[3] = acc[r][3];
        }
        __syncthreads();

        {
            int nl = tid >> 3, jb = tid & 7;
            int n = base + nl;
            float z = 0.f;
            #pragma unroll
            for (int jj = 0; jj < 8; jj++) {
                int j = jb * 8 + jj;
                float vg = sP[(0 * 32 + nl) * 65 + j] + sBia[j];
                float va2 = sP[(1 * 32 + nl) * 65 + j] + sBia[64 + j];
                z += fmaxf(vg, 0.f) * sWo[j] + fmaxf(va2, 0.f) * sWo[64 + j];
            }
            z += __shfl_down_sync(0xffffffffu, z, 4);
            z += __shfl_down_sync(0xffffffffu, z, 2);
            z += __shfl_down_sync(0xffffffffu, z, 1);
            if ((tid & 7) == 0 && n < N_NODES)
                g_z1[n] = z;
        }
    }
}

// ---------------- 5: kF2 — panels {aggS@Wl, x@Wr, (x+aggS)@Wi} + epilogue ----------------
// 384 thr = 12 warps = 3 panels x 4 node-groups(8). 75.3KB smem -> 3 blocks/SM.
// smem: sW[3][4096] @0, sWo[2][64] @12288, sBia[2][64] @12416, sCi[32] @12544,
//       union @12576: sU[3][64][32] (6144) / sP[3][32][65] (6240)
#define KF2_SMEM_FLOATS (12576 + 6240)
#define KF2_SMEM_BYTES (KF2_SMEM_FLOATS * 4)

__global__ void __launch_bounds__(384, 3) k_final2(
        const float* __restrict__ x,
        const float* __restrict__ Wl, const float* __restrict__ bl,
        const float* __restrict__ Wr,
        const float* __restrict__ Wi, const float* __restrict__ bi,
        const float* __restrict__ Wo, const float* __restrict__ bo,
        float* __restrict__ out) {
    extern __shared__ float sm[];
    float* sW   = sm;
    float* sWo  = sm + 12288;
    float* sBia = sm + 12416;
    float* sCi  = sm + 12544;
    float* sU   = sm + 12576;
    float* sP   = sm + 12576;
    int tid = threadIdx.x;

    for (int i = tid; i < 4096; i += 384) {
        sW[i]            = Wl[i];
        sW[4096 + i]     = Wr[i];
        sW[2 * 4096 + i] = Wi[i];
    }
    if (tid < 128) sWo[tid] = Wo[128 + tid];    // WoS | WoI
    if (tid < 64) { sBia[tid] = bl[tid]; sBia[64 + tid] = bi[tid]; }
    float bout = bo[0];
    __syncthreads();

    int wwid = tid >> 5, lane = tid & 31;
    int p = wwid >> 2, ng = wwid & 3;           // p in 0..2, ng in 0..3
    int tx = lane & 15, ty = lane >> 4;
    const float* Wp = sW + p * 4096;
    const float* Ub = sU + p * 2048 + ng * 8 + ty * 4;

    const float4* aggS4 = (const float4*)g_aggS;
    const float4* x4    = (const float4*)x;

    for (int tile = blockIdx.x; tile < N_TILES; tile += gridDim.x) {
        int base = tile * 32;
        __syncthreads();                        // previous tile's sP fully read
        if (tid < 32) {
            int n = base + tid;
            sCi[tid] = (n < N_NODES) ? 1.0f / fmaxf((float)g_cnt[n], 1.0f) : 0.f;
        }
        for (int idx = tid; idx < 1536; idx += 384) {
            int a = idx / 512, rem = idx & 511;
            int nl = rem & 31, kq = rem >> 5;
            int n = base + nl;
            float4 v = make_float4(0.f, 0.f, 0.f, 0.f);
            if (n < N_NODES) {
                if (a == 0) v = aggS4[n * 16 + kq];
                else if (a == 1) v = x4[n * 16 + kq];
                else {
                    float4 t1 = x4[n * 16 + kq];
                    float4 t2 = aggS4[n * 16 + kq];
                    v = make_float4(t1.x + t2.x, t1.y + t2.y, t1.z + t2.z, t1.w + t2.w);
                }
            }
            float* dstp = sU + a * 2048 + (kq * 4) * 32 + nl;
            dstp[0] = v.x; dstp[32] = v.y; dstp[64] = v.z; dstp[96] = v.w;
        }
        __syncthreads();

        float acc[4][4];
        #pragma unroll
        for (int r = 0; r < 4; r++)
            #pragma unroll
            for (int c = 0; c < 4; c++) acc[r][c] = 0.f;

        #pragma unroll 8
        for (int k = 0; k < 64; k++) {
            float4 u = *(const float4*)(Ub + k * 32);
            float4 wv = *(const float4*)(Wp + k * 64 + tx * 4);
            float ur[4] = {u.x, u.y, u.z, u.w};
            #pragma unroll
            for (int r = 0; r < 4; r++) {
                acc[r][0] = fmaf(ur[r], wv.x, acc[r][0]);
                acc[r][1] = fmaf(ur[r], wv.y, acc[r][1]);
                acc[r][2] = fmaf(ur[r], wv.z, acc[r][2]);
                acc[r][3] = fmaf(ur[r], wv.w, acc[r][3]);
            }
        }
        __syncthreads();                        // sU reads done before sP overwrite
        #pragma unroll
        for (int r = 0; r < 4; r++) {
            int nl = ng * 8 + ty * 4 + r;
            float* pp = sP + (p * 32 + nl) * 65 + tx * 4;
            pp[0] = acc[r][0]; pp[1] = acc[r][1]; pp[2] = acc[r][2]; pp[3] = acc[r][3];
        }
        __syncthreads();

        if (tid < 256) {
            int nl = tid >> 3, jb = tid & 7;
            int n = base + nl;
            float ci = sCi[nl];
            float z = 0.f;
            #pragma unroll
            for (int jj = 0; jj < 8; jj++) {
                int j = jb * 8 + jj;
                float vs = fmaf(ci, sP[(0 * 32 + nl) * 65 + j], sP[(1 * 32 + nl) * 65 + j]) + sBia[j];
                float vi = sP[(2 * 32 + nl) * 65 + j] + sBia[64 + j];
                z += fmaxf(vs, 0.f) * sWo[j] + fmaxf(vi, 0.f) * sWo[64 + j];
            }
            z += __shfl_down_sync(0xffffffffu, z, 4);
            z += __shfl_down_sync(0xffffffffu, z, 2);
            z += __shfl_down_sync(0xffffffffu, z, 1);
            if ((tid & 7) == 0 && n < N_NODES) {
                float zt = z + g_z1[n] + bout;
                out[n] = 1.0f / (1.0f + expf(-zt));
            }
        }
    }
}

// ---------------- launch ----------------
extern "C" void kernel_launch(void* const* d_in, const int* in_sizes, int n_in,
                              void* d_out, int out_size) {
    const float* x    = (const float*)d_in[0];
    const void*  ei   = d_in[1];
    const float* Wg   = (const float*)d_in[2];
    const float* bg   = (const float*)d_in[3];
    const float* Wa   = (const float*)d_in[4];
    const float* asrc = (const float*)d_in[5];
    const float* adst = (const float*)d_in[6];
    const float* ba   = (const float*)d_in[7];
    const float* Wl   = (const float*)d_in[8];
    const float* bl   = (const float*)d_in[9];
    const float* Wr   = (const float*)d_in[10];
    const float* Wi   = (const float*)d_in[11];
    const float* bi   = (const float*)d_in[12];
    const float* Wo   = (const float*)d_in[13];
    const float* bo   = (const float*)d_in[14];
    float* out = (float*)d_out;

    cudaFuncSetAttribute(k_final1, cudaFuncAttributeMaxDynamicSharedMemorySize, KF1_SMEM_BYTES);
    cudaFuncSetAttribute(k_final2, cudaFuncAttributeMaxDynamicSharedMemorySize, KF2_SMEM_BYTES);

    void* cnt_ptr = nullptr;
    cudaGetSymbolAddress(&cnt_ptr, g_cnt);
    cudaMemsetAsync(cnt_ptr, 0, (N_NODES + 1) * sizeof(int), 0);

    k_convert<<<2048, 256>>>(ei, x, Wa, asrc, adst);                       // 0
    k_rowassign<<<(N_NODES + 255) / 256, 256>>>();                         // 1
    k_scatter<<<1024, 256>>>();                                            // 2
    k_agg<<<(N_NODES * 32 + 255) / 256, 256>>>(x);                         // 3 (profiled)
    k_final1<<<592, 256, KF1_SMEM_BYTES>>>(Wg, bg, Wa, ba, Wo);            // 4
    k_final2<<<444, 384, KF2_SMEM_BYTES>>>(x, Wl, bl, Wr, Wi, bi,          // 5
                                           Wo, bo, out);
}

// round 14
// speedup vs baseline: 1.9157x; 1.3445x over previous
#include <cuda_runtime.h>
#include <cstdint>

#define N_NODES 50000
#define N_EDGES 800000
#define FDIM 64
#define N_TILES ((N_NODES + 31) / 32)   // 1563

// ---------------- device scratch ----------------
__device__ int   g_src[N_EDGES];
__device__ int   g_dst[N_EDGES];
__device__ int   g_csrc[N_EDGES];          // CSR: src ids grouped by dst
__device__ int   g_row[N_NODES];           // CSR slice start per dst (arbitrary order)
__device__ int   g_cnt[N_NODES + 1];       // in-degree histogram; [N] = global offset counter
__device__ int   g_cur[N_NODES];           // scatter cursors
__device__ __align__(16) float g_aggG[N_NODES * FDIM];
__device__ __align__(16) float g_aggA[N_NODES * FDIM];
__device__ __align__(16) float g_aggS[N_NODES * FDIM];
__device__ __align__(8)  float2 g_sd[N_NODES];   // {ssrc, dinv} packed for 1-LDG edge gather
__device__ float g_sdst[N_NODES];

__device__ __forceinline__ float lrelu(float v) { return v > 0.f ? v : 0.2f * v; }

__device__ __forceinline__ uint32_t f2tf32(float f) {
    uint32_t r;
    asm("cvt.rna.tf32.f32 %0, %1;" : "=r"(r) : "f"(f));
    return r;
}
__device__ __forceinline__ void mma_tf32(float c[4], const uint32_t a[4], const uint32_t b[2]) {
    asm("mma.sync.aligned.m16n8k8.row.col.f32.tf32.tf32.f32 "
        "{%0,%1,%2,%3},{%4,%5,%6,%7},{%8,%9},{%0,%1,%2,%3};"
        : "+f"(c[0]), "+f"(c[1]), "+f"(c[2]), "+f"(c[3])
        : "r"(a[0]), "r"(a[1]), "r"(a[2]), "r"(a[3]), "r"(b[0]), "r"(b[1]));
}

// ---------------- 0: dtype-detect + convert + histogram + per-node attn scalars ----------------
// int64 detection: ids < 50000 so high 32-bit words are 0; if int32, the odd
// words are 64 random ids (all-zero prob ~ (1/50000)^64 ~ 0).
__global__ void k_convert(const void* __restrict__ ei, const float* __restrict__ x,
                          const float* __restrict__ Wa, const float* __restrict__ as_,
                          const float* __restrict__ ad_) {
    __shared__ int s_is64;
    __shared__ float sva[FDIM], svb[FDIM];
    const unsigned int* w = (const unsigned int*)ei;
    int gid = blockIdx.x * blockDim.x + threadIdx.x;

    if (threadIdx.x == 0) {
        int z = 1;
        for (int i = 0; i < 64; i++) if (w[2 * i + 1] != 0u) { z = 0; break; }
        s_is64 = z;
    }
    if (blockIdx.x * blockDim.x < N_NODES) {
        if (threadIdx.x < FDIM) {
            int k = threadIdx.x;
            float va = 0.f, vb = 0.f;
            #pragma unroll 8
            for (int j = 0; j < FDIM; j++) {
                float wv = Wa[k * FDIM + j];
                va = fmaf(wv, as_[j], va);
                vb = fmaf(wv, ad_[j], vb);
            }
            sva[k] = va;
            svb[k] = vb;
        }
        __syncthreads();
        if (gid < N_NODES) {
            const float4* xr = (const float4*)(x + (size_t)gid * FDIM);
            float ss = 0.f, sd = 0.f;
            #pragma unroll
            for (int i = 0; i < FDIM / 4; i++) {
                float4 v = xr[i];
                ss = fmaf(v.x, sva[4*i], fmaf(v.y, sva[4*i+1], fmaf(v.z, sva[4*i+2], fmaf(v.w, sva[4*i+3], ss))));
                sd = fmaf(v.x, svb[4*i], fmaf(v.y, svb[4*i+1], fmaf(v.z, svb[4*i+2], fmaf(v.w, svb[4*i+3], sd))));
            }
            g_sd[gid].x = ss;
            g_sdst[gid] = sd;
        }
    } else {
        __syncthreads();
    }
    int is64 = s_is64;
    int stride = gridDim.x * blockDim.x;
    for (int i = gid; i < 2 * N_EDGES; i += stride) {
        int v;
        if (is64) v = (int)((const long long*)ei)[i];
        else      v = ((const int*)ei)[i];
        if (i < N_EDGES) g_src[i] = v;
        else {
            g_dst[i - N_EDGES] = v;
            atomicAdd(&g_cnt[v], 1);
        }
    }
}

// ---------------- 1: row-slice assignment (block scan + 1 atomic per block) ----------------
__global__ void k_rowassign() {
    __shared__ int s_warp[8];
    __shared__ int s_base;
    int tid = threadIdx.x;
    int n = blockIdx.x * 256 + tid;
    int lane = tid & 31, wid = tid >> 5;
    int c = (n < N_NODES) ? g_cnt[n] : 0;
    int v = c;
    #pragma unroll
    for (int off = 1; off < 32; off <<= 1) {
        int u = __shfl_up_sync(0xffffffffu, v, off);
        if (lane >= off) v += u;
    }
    if (lane == 31) s_warp[wid] = v;
    __syncthreads();
    if (tid < 8) {
        int pv = s_warp[tid];
        #pragma unroll
        for (int off = 1; off < 8; off <<= 1) {
            int u = __shfl_up_sync(0xffu, pv, off);
            if (tid >= off) pv += u;
        }
        s_warp[tid] = pv;
        if (tid == 7) s_base = atomicAdd(&g_cnt[N_NODES], pv);
    }
    __syncthreads();
    int excl = v - c + (wid > 0 ? s_warp[wid - 1] : 0);
    if (n < N_NODES) {
        g_row[n] = s_base + excl;
        g_cur[n] = 0;
        g_sd[n].y = rsqrtf((float)c + 1.0f);
    }
}

// ---------------- 2: scatter src into CSR ----------------
__global__ void k_scatter() {
    int stride = gridDim.x * blockDim.x;
    for (int e = blockIdx.x * blockDim.x + threadIdx.x; e < N_EDGES; e += stride) {
        int d = g_dst[e];
        int pos = g_row[d] + atomicAdd(&g_cur[d], 1);
        g_csrc[pos] = g_src[e];
    }
}

// ---------------- 3: warp-per-node aggregation (R12 measured-best: 38 regs) ----------------
__global__ void __launch_bounds__(256) k_agg(const float* __restrict__ x) {
    int wid = (blockIdx.x * blockDim.x + threadIdx.x) >> 5;
    int lane = threadIdx.x & 31;
    if (wid >= N_NODES) return;
    int d = wid;
    int row = g_row[d], end = row + g_cnt[d];
    float sd = g_sdst[d];
    float2 dsd = g_sd[d];
    float dvd = dsd.y;
    int q = lane & 15, half = lane >> 4;

    float4 aG = make_float4(0.f, 0.f, 0.f, 0.f);
    float4 aA = aG, aS = aG;
    float denom = 0.f;

    for (int base = row; base < end; base += 32) {
        int m = min(32, end - base);
        int   s_r = 0;
        float we_r = 0.f, wg_r = 0.f;
        if (lane < m) {
            s_r = g_csrc[base + lane];
            float2 sv = g_sd[s_r];
            we_r = expf(lrelu(sv.x + sd));
            wg_r = sv.y * dvd;
            denom += we_r;
        }
        for (int i2 = 0; i2 < m; i2 += 2) {
            int i = i2 + half;
            int ic = (i < m) ? i : 0;
            int   s  = __shfl_sync(0xffffffffu, s_r, ic);
            float we = __shfl_sync(0xffffffffu, we_r, ic);
            float wg = __shfl_sync(0xffffffffu, wg_r, ic);
            if (i < m) {
                float4 xv = ((const float4*)x)[s * 16 + q];
                aG.x = fmaf(wg, xv.x, aG.x); aG.y = fmaf(wg, xv.y, aG.y);
                aG.z = fmaf(wg, xv.z, aG.z); aG.w = fmaf(wg, xv.w, aG.w);
                aA.x = fmaf(we, xv.x, aA.x); aA.y = fmaf(we, xv.y, aA.y);
                aA.z = fmaf(we, xv.z, aA.z); aA.w = fmaf(we, xv.w, aA.w);
                aS.x += xv.x; aS.y += xv.y; aS.z += xv.z; aS.w += xv.w;
            }
        }
    }

    #pragma unroll
    for (int off = 16; off > 0; off >>= 1)
        denom += __shfl_xor_sync(0xffffffffu, denom, off);
    float selfexp = expf(lrelu(dsd.x + sd));
    float rdenom = 1.0f / (denom + selfexp);

    #pragma unroll
    for (int c = 0; c < 12; c++) {
        float* p = (c < 4) ? (&aG.x + c) : (c < 8) ? (&aA.x + (c - 4)) : (&aS.x + (c - 8));
        *p += __shfl_xor_sync(0xffffffffu, *p, 16);
    }
    if (half == 0) {
        float4 xd = ((const float4*)x)[d * 16 + q];
        float wd = dvd * dvd;
        float4 G = make_float4(fmaf(wd, xd.x, aG.x), fmaf(wd, xd.y, aG.y),
                               fmaf(wd, xd.z, aG.z), fmaf(wd, xd.w, aG.w));
        float4 A = make_float4((aA.x + selfexp * xd.x) * rdenom, (aA.y + selfexp * xd.y) * rdenom,
                               (aA.z + selfexp * xd.z) * rdenom, (aA.w + selfexp * xd.w) * rdenom);
        ((float4*)g_aggG)[d * 16 + q] = G;
        ((float4*)g_aggA)[d * 16 + q] = A;
        ((float4*)g_aggS)[d * 16 + q] = aS;
    }
}

// ---------------- 4: tensor-core k_final (tf32 mma.sync) ----------------
// 640 thr = 20 warps = 5 panels x 4 N-quarters(16). Weights live in registers as
// tf32 B fragments (32 regs/lane, loaded once). Per 32-node tile: stage tf32
// inputs to sU (stride 68 = conflict-free A-frag LDS), 32 mma per warp, C to sP,
// fused relu/head/sigmoid epilogue.
// panels: 0 aggG@Wg  1 aggA@Wa  2 (ci*aggS)@Wl  3 x@Wr  4 (x+aggS)@Wi
// smem floats: sU[5][32][68] @0 (10880) | sP[5][32][68] @10880 (10880)
//              sWo[4][64] @21760 | sBia[4][64] @22016 | sCi[32] @22272
#define PSZ 2176                       // 32*68
#define KT_SMEM_FLOATS (21760 + 256 + 256 + 32)
#define KT_SMEM_BYTES (KT_SMEM_FLOATS * 4)

__global__ void __launch_bounds__(640, 1) k_final_tc(
        const float* __restrict__ x,
        const float* __restrict__ Wg, const float* __restrict__ bg,
        const float* __restrict__ Wa, const float* __restrict__ ba,
        const float* __restrict__ Wl, const float* __restrict__ bl,
        const float* __restrict__ Wr,
        const float* __restrict__ Wi, const float* __restrict__ bi,
        const float* __restrict__ Wo, const float* __restrict__ bo,
        float* __restrict__ out) {
    extern __shared__ float sm[];
    float* sU   = sm;
    float* sP   = sm + 10880;
    float* sWo  = sm + 21760;
    float* sBia = sm + 22016;
    float* sCi  = sm + 22272;
    int tid = threadIdx.x;
    int wwid = tid >> 5, lane = tid & 31;
    int p = wwid >> 2, nq = wwid & 3;
    int lg = lane >> 2, lt = lane & 3;      // group row / thread-in-group

    if (tid < 256) sWo[tid] = Wo[tid];
    if (tid < 64) {
        sBia[tid] = bg[tid]; sBia[64 + tid] = ba[tid];
        sBia[128 + tid] = bl[tid]; sBia[192 + tid] = bi[tid];
    }
    float bout = bo[0];

    // B fragments in registers (one panel weight matrix per warp group of 4)
    const float* Wsrc = (p == 0) ? Wg : (p == 1) ? Wa : (p == 2) ? Wl : (p == 3) ? Wr : Wi;
    uint32_t bf[8][2][2];
    #pragma unroll
    for (int kc = 0; kc < 8; kc++)
        #pragma unroll
        for (int nc = 0; nc < 2; nc++) {
            int n = nq * 16 + nc * 8 + lg;
            int k0 = kc * 8 + lt;
            bf[kc][nc][0] = f2tf32(Wsrc[k0 * 64 + n]);
            bf[kc][nc][1] = f2tf32(Wsrc[(k0 + 4) * 64 + n]);
        }
    __syncthreads();

    const float4* aggG4 = (const float4*)g_aggG;
    const float4* aggA4 = (const float4*)g_aggA;
    const float4* aggS4 = (const float4*)g_aggS;
    const float4* x4    = (const float4*)x;
    float* sUp = sU + p * PSZ;
    float* sPp = sP + p * PSZ;

    for (int tile = blockIdx.x; tile < N_TILES; tile += gridDim.x) {
        int base = tile * 32;
        if (tid < 32) {
            int n = base + tid;
            sCi[tid] = (n < N_NODES) ? 1.0f / fmaxf((float)g_cnt[n], 1.0f) : 0.f;
        }
        __syncthreads();
        // stage tf32 inputs: 5 panels x 32 nodes x 16 float4-chunks
        for (int idx = tid; idx < 2560; idx += 640) {
            int a = idx >> 9, rem = idx & 511;
            int nl = rem & 31, kq = rem >> 5;
            int n = base + nl;
            float4 v = make_float4(0.f, 0.f, 0.f, 0.f);
            if (n < N_NODES) {
                if (a == 0) v = aggG4[n * 16 + kq];
                else if (a == 1) v = aggA4[n * 16 + kq];
                else if (a == 2) {
                    v = aggS4[n * 16 + kq];
                    float ci = sCi[nl];
                    v.x *= ci; v.y *= ci; v.z *= ci; v.w *= ci;
                } else if (a == 3) v = x4[n * 16 + kq];
                else {
                    float4 t1 = x4[n * 16 + kq];
                    float4 t2 = aggS4[n * 16 + kq];
                    v = make_float4(t1.x + t2.x, t1.y + t2.y, t1.z + t2.z, t1.w + t2.w);
                }
            }
            uint4 tv = make_uint4(f2tf32(v.x), f2tf32(v.y), f2tf32(v.z), f2tf32(v.w));
            *(uint4*)(sU + a * PSZ + nl * 68 + kq * 4) = tv;
        }
        __syncthreads();

        // mma phase: per warp, 2 M-chunks x 2 N-chunks x 8 K-chunks
        #pragma unroll
        for (int mc = 0; mc < 2; mc++) {
            float c0[4] = {0.f, 0.f, 0.f, 0.f};
            float c1[4] = {0.f, 0.f, 0.f, 0.f};
            int row = mc * 16 + lg;
            #pragma unroll
            for (int kc = 0; kc < 8; kc++) {
                uint32_t af[4];
                int col = kc * 8 + lt;
                af[0] = __float_as_uint(sUp[row * 68 + col]);
                af[1] = __float_as_uint(sUp[(row + 8) * 68 + col]);
                af[2] = __float_as_uint(sUp[row * 68 + col + 4]);
                af[3] = __float_as_uint(sUp[(row + 8) * 68 + col + 4]);
                mma_tf32(c0, af, bf[kc][0]);
                mma_tf32(c1, af, bf[kc][1]);
            }
            #pragma unroll
            for (int nc = 0; nc < 2; nc++) {
                float* c = (nc == 0) ? c0 : c1;
                int node = mc * 16 + lg;
                int jg = nq * 16 + nc * 8 + 2 * lt;
                sPp[node * 68 + jg] = c[0];
                sPp[node * 68 + jg + 1] = c[1];
                sPp[(node + 8) * 68 + jg] = c[2];
                sPp[(node + 8) * 68 + jg + 1] = c[3];
            }
        }
        __syncthreads();

        // epilogue: relu per branch, out head, sigmoid
        if (tid < 512) {
            int nl = tid >> 4, jb = tid & 15;
            int n = base + nl;
            float z = 0.f;
            #pragma unroll
            for (int jj = 0; jj < 4; jj++) {
                int j = jb * 4 + jj;
                float vg = sP[0 * PSZ + nl * 68 + j] + sBia[j];
                float va2 = sP[1 * PSZ + nl * 68 + j] + sBia[64 + j];
                float vs = sP[2 * PSZ + nl * 68 + j] + sP[3 * PSZ + nl * 68 + j] + sBia[128 + j];
                float vi = sP[4 * PSZ + nl * 68 + j] + sBia[192 + j];
                z += fmaxf(vg, 0.f) * sWo[j] + fmaxf(va2, 0.f) * sWo[64 + j]
                   + fmaxf(vs, 0.f) * sWo[128 + j] + fmaxf(vi, 0.f) * sWo[192 + j];
            }
            z += __shfl_down_sync(0xffffffffu, z, 8, 16);
            z += __shfl_down_sync(0xffffffffu, z, 4, 16);
            z += __shfl_down_sync(0xffffffffu, z, 2, 16);
            z += __shfl_down_sync(0xffffffffu, z, 1, 16);
            if (jb == 0 && n < N_NODES)
                out[n] = 1.0f / (1.0f + expf(-(z + bout)));
        }
        __syncthreads();
    }
}

// ---------------- launch ----------------
extern "C" void kernel_launch(void* const* d_in, const int* in_sizes, int n_in,
                              void* d_out, int out_size) {
    const float* x    = (const float*)d_in[0];
    const void*  ei   = d_in[1];
    const float* Wg   = (const float*)d_in[2];
    const float* bg   = (const float*)d_in[3];
    const float* Wa   = (const float*)d_in[4];
    const float* asrc = (const float*)d_in[5];
    const float* adst = (const float*)d_in[6];
    const float* ba   = (const float*)d_in[7];
    const float* Wl   = (const float*)d_in[8];
    const float* bl   = (const float*)d_in[9];
    const float* Wr   = (const float*)d_in[10];
    const float* Wi   = (const float*)d_in[11];
    const float* bi   = (const float*)d_in[12];
    const float* Wo   = (const float*)d_in[13];
    const float* bo   = (const float*)d_in[14];
    float* out = (float*)d_out;

    cudaFuncSetAttribute(k_final_tc, cudaFuncAttributeMaxDynamicSharedMemorySize, KT_SMEM_BYTES);

    void* cnt_ptr = nullptr;
    cudaGetSymbolAddress(&cnt_ptr, g_cnt);
    cudaMemsetAsync(cnt_ptr, 0, (N_NODES + 1) * sizeof(int), 0);

    k_convert<<<2048, 256>>>(ei, x, Wa, asrc, adst);                       // 0
    k_rowassign<<<(N_NODES + 255) / 256, 256>>>();                         // 1
    k_scatter<<<1024, 256>>>();                                            // 2
    k_agg<<<(N_NODES * 32 + 255) / 256, 256>>>(x);                         // 3 (profiled)
    k_final_tc<<<148, 640, KT_SMEM_BYTES>>>(x, Wg, bg, Wa, ba, Wl, bl,     // 4
                                            Wr, Wi, bi, Wo, bo, out);
}

// round 15
// speedup vs baseline: 2.1202x; 1.1068x over previous
#include <cuda_runtime.h>
#include <cstdint>

#define N_NODES 50000
#define N_EDGES 800000
#define FDIM 64
#define N_TILES ((N_NODES + 31) / 32)   // 1563

// ---------------- device scratch ----------------
__device__ int   g_src[N_EDGES];
__device__ int   g_dst[N_EDGES];
__device__ int   g_csrc[N_EDGES];          // CSR: src ids grouped by dst
__device__ int   g_row[N_NODES];           // CSR slice start per dst (arbitrary order)
__device__ int   g_cnt[N_NODES + 1];       // in-degree histogram; [N] = global offset counter
__device__ int   g_cur[N_NODES];           // scatter cursors
__device__ __align__(16) float g_aggG[N_NODES * FDIM];
__device__ __align__(16) float g_aggA[N_NODES * FDIM];
__device__ __align__(16) float g_aggS[N_NODES * FDIM];
__device__ __align__(8)  float2 g_sd[N_NODES];   // {ssrc, dinv} packed for 1-LDG edge gather
__device__ float g_sdst[N_NODES];

__device__ __forceinline__ float lrelu(float v) { return v > 0.f ? v : 0.2f * v; }

__device__ __forceinline__ void mma_tf32(float c[4], const uint32_t a[4], const uint32_t b[2]) {
    asm("mma.sync.aligned.m16n8k8.row.col.f32.tf32.tf32.f32 "
        "{%0,%1,%2,%3},{%4,%5,%6,%7},{%8,%9},{%0,%1,%2,%3};"
        : "+f"(c[0]), "+f"(c[1]), "+f"(c[2]), "+f"(c[3])
        : "r"(a[0]), "r"(a[1]), "r"(a[2]), "r"(a[3]), "r"(b[0]), "r"(b[1]));
}
__device__ __forceinline__ uint32_t f2tf32(float f) {
    uint32_t r;
    asm("cvt.rna.tf32.f32 %0, %1;" : "=r"(r) : "f"(f));
    return r;
}
__device__ __forceinline__ void cp_async16(uint32_t dst, const void* src) {
    asm volatile("cp.async.cg.shared.global [%0], [%1], 16;" :: "r"(dst), "l"(src) : "memory");
}

// ---------------- 0: dtype-detect + convert + histogram + per-node attn scalars ----------------
// int64 detection: ids < 50000 so high 32-bit words are 0; if int32, the odd
// words are 64 random ids (all-zero prob ~ (1/50000)^64 ~ 0).
__global__ void k_convert(const void* __restrict__ ei, const float* __restrict__ x,
                          const float* __restrict__ Wa, const float* __restrict__ as_,
                          const float* __restrict__ ad_) {
    __shared__ int s_is64;
    __shared__ float sva[FDIM], svb[FDIM];
    const unsigned int* w = (const unsigned int*)ei;
    int gid = blockIdx.x * blockDim.x + threadIdx.x;

    if (threadIdx.x == 0) {
        int z = 1;
        for (int i = 0; i < 64; i++) if (w[2 * i + 1] != 0u) { z = 0; break; }
        s_is64 = z;
    }
    if (blockIdx.x * blockDim.x < N_NODES) {
        if (threadIdx.x < FDIM) {
            int k = threadIdx.x;
            float va = 0.f, vb = 0.f;
            #pragma unroll 8
            for (int j = 0; j < FDIM; j++) {
                float wv = Wa[k * FDIM + j];
                va = fmaf(wv, as_[j], va);
                vb = fmaf(wv, ad_[j], vb);
            }
            sva[k] = va;
            svb[k] = vb;
        }
        __syncthreads();
        if (gid < N_NODES) {
            const float4* xr = (const float4*)(x + (size_t)gid * FDIM);
            float ss = 0.f, sd = 0.f;
            #pragma unroll
            for (int i = 0; i < FDIM / 4; i++) {
                float4 v = xr[i];
                ss = fmaf(v.x, sva[4*i], fmaf(v.y, sva[4*i+1], fmaf(v.z, sva[4*i+2], fmaf(v.w, sva[4*i+3], ss))));
                sd = fmaf(v.x, svb[4*i], fmaf(v.y, svb[4*i+1], fmaf(v.z, svb[4*i+2], fmaf(v.w, svb[4*i+3], sd))));
            }
            g_sd[gid].x = ss;
            g_sdst[gid] = sd;
        }
    } else {
        __syncthreads();
    }
    int is64 = s_is64;
    int stride = gridDim.x * blockDim.x;
    for (int i = gid; i < 2 * N_EDGES; i += stride) {
        int v;
        if (is64) v = (int)((const long long*)ei)[i];
        else      v = ((const int*)ei)[i];
        if (i < N_EDGES) g_src[i] = v;
        else {
            g_dst[i - N_EDGES] = v;
            atomicAdd(&g_cnt[v], 1);
        }
    }
}

// ---------------- 1: row-slice assignment (block scan + 1 atomic per block) ----------------
__global__ void k_rowassign() {
    __shared__ int s_warp[8];
    __shared__ int s_base;
    int tid = threadIdx.x;
    int n = blockIdx.x * 256 + tid;
    int lane = tid & 31, wid = tid >> 5;
    int c = (n < N_NODES) ? g_cnt[n] : 0;
    int v = c;
    #pragma unroll
    for (int off = 1; off < 32; off <<= 1) {
        int u = __shfl_up_sync(0xffffffffu, v, off);
        if (lane >= off) v += u;
    }
    if (lane == 31) s_warp[wid] = v;
    __syncthreads();
    if (tid < 8) {
        int pv = s_warp[tid];
        #pragma unroll
        for (int off = 1; off < 8; off <<= 1) {
            int u = __shfl_up_sync(0xffu, pv, off);
            if (tid >= off) pv += u;
        }
        s_warp[tid] = pv;
        if (tid == 7) s_base = atomicAdd(&g_cnt[N_NODES], pv);
    }
    __syncthreads();
    int excl = v - c + (wid > 0 ? s_warp[wid - 1] : 0);
    if (n < N_NODES) {
        g_row[n] = s_base + excl;
        g_cur[n] = 0;
        g_sd[n].y = rsqrtf((float)c + 1.0f);
    }
}

// ---------------- 2: scatter src into CSR ----------------
__global__ void k_scatter() {
    int stride = gridDim.x * blockDim.x;
    for (int e = blockIdx.x * blockDim.x + threadIdx.x; e < N_EDGES; e += stride) {
        int d = g_dst[e];
        int pos = g_row[d] + atomicAdd(&g_cur[d], 1);
        g_csrc[pos] = g_src[e];
    }
}

// ---------------- 3: warp-per-node aggregation (R12 measured-best: 38 regs) ----------------
__global__ void __launch_bounds__(256) k_agg(const float* __restrict__ x) {
    int wid = (blockIdx.x * blockDim.x + threadIdx.x) >> 5;
    int lane = threadIdx.x & 31;
    if (wid >= N_NODES) return;
    int d = wid;
    int row = g_row[d], end = row + g_cnt[d];
    float sd = g_sdst[d];
    float2 dsd = g_sd[d];
    float dvd = dsd.y;
    int q = lane & 15, half = lane >> 4;

    float4 aG = make_float4(0.f, 0.f, 0.f, 0.f);
    float4 aA = aG, aS = aG;
    float denom = 0.f;

    for (int base = row; base < end; base += 32) {
        int m = min(32, end - base);
        int   s_r = 0;
        float we_r = 0.f, wg_r = 0.f;
        if (lane < m) {
            s_r = g_csrc[base + lane];
            float2 sv = g_sd[s_r];
            we_r = expf(lrelu(sv.x + sd));
            wg_r = sv.y * dvd;
            denom += we_r;
        }
        for (int i2 = 0; i2 < m; i2 += 2) {
            int i = i2 + half;
            int ic = (i < m) ? i : 0;
            int   s  = __shfl_sync(0xffffffffu, s_r, ic);
            float we = __shfl_sync(0xffffffffu, we_r, ic);
            float wg = __shfl_sync(0xffffffffu, wg_r, ic);
            if (i < m) {
                float4 xv = ((const float4*)x)[s * 16 + q];
                aG.x = fmaf(wg, xv.x, aG.x); aG.y = fmaf(wg, xv.y, aG.y);
                aG.z = fmaf(wg, xv.z, aG.z); aG.w = fmaf(wg, xv.w, aG.w);
                aA.x = fmaf(we, xv.x, aA.x); aA.y = fmaf(we, xv.y, aA.y);
                aA.z = fmaf(we, xv.z, aA.z); aA.w = fmaf(we, xv.w, aA.w);
                aS.x += xv.x; aS.y += xv.y; aS.z += xv.z; aS.w += xv.w;
            }
        }
    }

    #pragma unroll
    for (int off = 16; off > 0; off >>= 1)
        denom += __shfl_xor_sync(0xffffffffu, denom, off);
    float selfexp = expf(lrelu(dsd.x + sd));
    float rdenom = 1.0f / (denom + selfexp);

    #pragma unroll
    for (int c = 0; c < 12; c++) {
        float* p = (c < 4) ? (&aG.x + c) : (c < 8) ? (&aA.x + (c - 4)) : (&aS.x + (c - 8));
        *p += __shfl_xor_sync(0xffffffffu, *p, 16);
    }
    if (half == 0) {
        float4 xd = ((const float4*)x)[d * 16 + q];
        float wd = dvd * dvd;
        float4 G = make_float4(fmaf(wd, xd.x, aG.x), fmaf(wd, xd.y, aG.y),
                               fmaf(wd, xd.z, aG.z), fmaf(wd, xd.w, aG.w));
        float4 A = make_float4((aA.x + selfexp * xd.x) * rdenom, (aA.y + selfexp * xd.y) * rdenom,
                               (aA.z + selfexp * xd.z) * rdenom, (aA.w + selfexp * xd.w) * rdenom);
        ((float4*)g_aggG)[d * 16 + q] = G;
        ((float4*)g_aggA)[d * 16 + q] = A;
        ((float4*)g_aggS)[d * 16 + q] = aS;
    }
}

// ---------------- 4: tensor-core k_final, cp.async double-buffered ----------------
// 768 thr = 24 warps = 6 panels x 4 N-quarters(16).
// panels: 0 aggG@Wg  1 aggA@Wa  2 aggS@Wl  3 aggS@Wi  4 x@Wr  5 x@Wi
// input arrays (raw f32 staged by cp.async; mma.tf32 truncates = RZ):
//   0 aggG  1 aggA  2 aggS  3 x ; panel->array {0,1,2,2,3,3}
// epilogue: SAGE = ci*P2 + P4 + bl ; GIN = P3 + P5 + bi
// smem floats: sU[2][4][2176] @0 (17408) | sP[6][2176] @17408 (13056)
//              sWo[4][64] @30464 | sBia[4][64] @30720 | sCi[32] @30976
#define PSZ 2176                       // 32*68
#define UBUF 8704                      // 4*2176
#define KT_SMEM_FLOATS (17408 + 13056 + 256 + 256 + 32)
#define KT_SMEM_BYTES (KT_SMEM_FLOATS * 4)

__global__ void __launch_bounds__(768, 1) k_final_tc(
        const float* __restrict__ x,
        const float* __restrict__ Wg, const float* __restrict__ bg,
        const float* __restrict__ Wa, const float* __restrict__ ba,
        const float* __restrict__ Wl, const float* __restrict__ bl,
        const float* __restrict__ Wr,
        const float* __restrict__ Wi, const float* __restrict__ bi,
        const float* __restrict__ Wo, const float* __restrict__ bo,
        float* __restrict__ out) {
    extern __shared__ float sm[];
    float* sU   = sm;
    float* sP   = sm + 17408;
    float* sWo  = sm + 30464;
    float* sBia = sm + 30720;
    float* sCi  = sm + 30976;
    int tid = threadIdx.x;
    int wwid = tid >> 5, lane = tid & 31;
    int p = wwid >> 2, nq = wwid & 3;
    int lg = lane >> 2, lt = lane & 3;
    uint32_t sU_u32 = (uint32_t)__cvta_generic_to_shared(sU);

    const float4* gsrc[4] = { (const float4*)g_aggG, (const float4*)g_aggA,
                              (const float4*)g_aggS, (const float4*)x };

    // prefetch tile 0 into buffer 0
    {
        int base = blockIdx.x * 32;
        for (int idx = tid; idx < 2048; idx += 768) {
            int a = idx >> 9, rem = idx & 511;
            int nl = rem & 31, kq = rem >> 5;
            int nn = min(base + nl, N_NODES - 1);
            cp_async16(sU_u32 + (a * PSZ + nl * 68 + kq * 4) * 4, gsrc[a] + nn * 16 + kq);
        }
        asm volatile("cp.async.commit_group;" ::: "memory");
    }

    if (tid < 256) sWo[tid] = Wo[tid];
    if (tid < 64) {
        sBia[tid] = bg[tid]; sBia[64 + tid] = ba[tid];
        sBia[128 + tid] = bl[tid]; sBia[192 + tid] = bi[tid];
    }
    float bout = bo[0];

    // B fragments in registers (one weight matrix per panel warp-group)
    const float* Wsrc = (p == 0) ? Wg : (p == 1) ? Wa : (p == 2) ? Wl
                      : (p == 3) ? Wi : (p == 4) ? Wr : Wi;
    uint32_t bf[8][2][2];
    #pragma unroll
    for (int kc = 0; kc < 8; kc++)
        #pragma unroll
        for (int nc = 0; nc < 2; nc++) {
            int n = nq * 16 + nc * 8 + lg;
            int k0 = kc * 8 + lt;
            bf[kc][nc][0] = f2tf32(Wsrc[k0 * 64 + n]);
            bf[kc][nc][1] = f2tf32(Wsrc[(k0 + 4) * 64 + n]);
        }

    int ain = (p <= 1) ? p : (p <= 3) ? 2 : 3;
    int buf = 0;
    for (int tile = blockIdx.x; tile < N_TILES; tile += gridDim.x) {
        int base = tile * 32;
        int nxt = tile + gridDim.x;
        if (nxt < N_TILES) {
            int nbase = nxt * 32;
            int noff = (buf ^ 1) * UBUF;
            for (int idx = tid; idx < 2048; idx += 768) {
                int a = idx >> 9, rem = idx & 511;
                int nl = rem & 31, kq = rem >> 5;
                int nn = min(nbase + nl, N_NODES - 1);
                cp_async16(sU_u32 + (noff + a * PSZ + nl * 68 + kq * 4) * 4,
                           gsrc[a] + nn * 16 + kq);
            }
            asm volatile("cp.async.commit_group;" ::: "memory");
            asm volatile("cp.async.wait_group 1;" ::: "memory");
        } else {
            asm volatile("cp.async.wait_group 0;" ::: "memory");
        }
        __syncthreads();                   // current buffer ready; prev epilogue done

        if (tid < 32) {
            int n = base + tid;
            sCi[tid] = (n < N_NODES) ? 1.0f / fmaxf((float)g_cnt[n], 1.0f) : 0.f;
        }

        // mma: 2 M-chunks x 2 N-chunks x 8 K-chunks per warp
        const float* sUp = sU + buf * UBUF + ain * PSZ;
        float* sPp = sP + p * PSZ;
        #pragma unroll
        for (int mc = 0; mc < 2; mc++) {
            float c0[4] = {0.f, 0.f, 0.f, 0.f};
            float c1[4] = {0.f, 0.f, 0.f, 0.f};
            int row = mc * 16 + lg;
            #pragma unroll
            for (int kc = 0; kc < 8; kc++) {
                uint32_t af[4];
                int col = kc * 8 + lt;
                af[0] = __float_as_uint(sUp[row * 68 + col]);
                af[1] = __float_as_uint(sUp[(row + 8) * 68 + col]);
                af[2] = __float_as_uint(sUp[row * 68 + col + 4]);
                af[3] = __float_as_uint(sUp[(row + 8) * 68 + col + 4]);
                mma_tf32(c0, af, bf[kc][0]);
                mma_tf32(c1, af, bf[kc][1]);
            }
            #pragma unroll
            for (int nc = 0; nc < 2; nc++) {
                float* c = (nc == 0) ? c0 : c1;
                int node = mc * 16 + lg;
                int jg = nq * 16 + nc * 8 + 2 * lt;
                sPp[node * 68 + jg] = c[0];
                sPp[node * 68 + jg + 1] = c[1];
                sPp[(node + 8) * 68 + jg] = c[2];
                sPp[(node + 8) * 68 + jg + 1] = c[3];
            }
        }
        __syncthreads();

        // epilogue: relu per branch, out head, sigmoid
        if (tid < 512) {
            int nl = tid >> 4, jb = tid & 15;
            int n = base + nl;
            float ci = sCi[nl];
            float z = 0.f;
            #pragma unroll
            for (int jj = 0; jj < 4; jj++) {
                int j = jb * 4 + jj;
                float vg = sP[0 * PSZ + nl * 68 + j] + sBia[j];
                float va2 = sP[1 * PSZ + nl * 68 + j] + sBia[64 + j];
                float vs = fmaf(ci, sP[2 * PSZ + nl * 68 + j], sP[4 * PSZ + nl * 68 + j]) + sBia[128 + j];
                float vi = sP[3 * PSZ + nl * 68 + j] + sP[5 * PSZ + nl * 68 + j] + sBia[192 + j];
                z += fmaxf(vg, 0.f) * sWo[j] + fmaxf(va2, 0.f) * sWo[64 + j]
                   + fmaxf(vs, 0.f) * sWo[128 + j] + fmaxf(vi, 0.f) * sWo[192 + j];
            }
            z += __shfl_down_sync(0xffffffffu, z, 8, 16);
            z += __shfl_down_sync(0xffffffffu, z, 4, 16);
            z += __shfl_down_sync(0xffffffffu, z, 2, 16);
            z += __shfl_down_sync(0xffffffffu, z, 1, 16);
            if (jb == 0 && n < N_NODES)
                out[n] = 1.0f / (1.0f + expf(-(z + bout)));
        }
        __syncthreads();                   // sP/sCi reads done before next tile
        buf ^= 1;
    }
}

// ---------------- launch ----------------
extern "C" void kernel_launch(void* const* d_in, const int* in_sizes, int n_in,
                              void* d_out, int out_size) {
    const float* x    = (const float*)d_in[0];
    const void*  ei   = d_in[1];
    const float* Wg   = (const float*)d_in[2];
    const float* bg   = (const float*)d_in[3];
    const float* Wa   = (const float*)d_in[4];
    const float* asrc = (const float*)d_in[5];
    const float* adst = (const float*)d_in[6];
    const float* ba   = (const float*)d_in[7];
    const float* Wl   = (const float*)d_in[8];
    const float* bl   = (const float*)d_in[9];
    const float* Wr   = (const float*)d_in[10];
    const float* Wi   = (const float*)d_in[11];
    const float* bi   = (const float*)d_in[12];
    const float* Wo   = (const float*)d_in[13];
    const float* bo   = (const float*)d_in[14];
    float* out = (float*)d_out;

    cudaFuncSetAttribute(k_final_tc, cudaFuncAttributeMaxDynamicSharedMemorySize, KT_SMEM_BYTES);

    void* cnt_ptr = nullptr;
    cudaGetSymbolAddress(&cnt_ptr, g_cnt);
    cudaMemsetAsync(cnt_ptr, 0, (N_NODES + 1) * sizeof(int), 0);

    k_convert<<<2048, 256>>>(ei, x, Wa, asrc, adst);                       // 0
    k_rowassign<<<(N_NODES + 255) / 256, 256>>>();                         // 1
    k_scatter<<<1024, 256>>>();                                            // 2
    k_agg<<<(N_NODES * 32 + 255) / 256, 256>>>(x);                         // 3 (profiled)
    k_final_tc<<<148, 768, KT_SMEM_BYTES>>>(x, Wg, bg, Wa, ba, Wl, bl,     // 4
                                            Wr, Wi, bi, Wo, bo, out);
}

// round 16
// speedup vs baseline: 2.1610x; 1.0193x over previous
#include <cuda_runtime.h>
#include <cstdint>

#define N_NODES 50000
#define N_EDGES 800000
#define FDIM 64
#define N_TILES ((N_NODES + 31) / 32)   // 1563

// ---------------- device scratch ----------------
__device__ __align__(8) int2 g_edge[N_EDGES];   // packed (src, dst)
__device__ int   g_csrc[N_EDGES];          // CSR: src ids grouped by dst
__device__ int   g_row[N_NODES];           // CSR slice start per dst (arbitrary order)
__device__ int   g_cnt[N_NODES + 1];       // in-degree histogram; [N] = global offset counter
__device__ int   g_cur[N_NODES];           // scatter cursors
__device__ __align__(16) float g_aggG[N_NODES * FDIM];
__device__ __align__(16) float g_aggA[N_NODES * FDIM];
__device__ __align__(16) float g_aggS[N_NODES * FDIM];
__device__ __align__(8)  float2 g_sd[N_NODES];   // {ssrc, dinv} packed for 1-LDG edge gather
__device__ float g_sdst[N_NODES];

__device__ __forceinline__ float lrelu(float v) { return v > 0.f ? v : 0.2f * v; }

__device__ __forceinline__ void mma_tf32(float c[4], const uint32_t a[4], const uint32_t b[2]) {
    asm("mma.sync.aligned.m16n8k8.row.col.f32.tf32.tf32.f32 "
        "{%0,%1,%2,%3},{%4,%5,%6,%7},{%8,%9},{%0,%1,%2,%3};"
        : "+f"(c[0]), "+f"(c[1]), "+f"(c[2]), "+f"(c[3])
        : "r"(a[0]), "r"(a[1]), "r"(a[2]), "r"(a[3]), "r"(b[0]), "r"(b[1]));
}
__device__ __forceinline__ uint32_t f2tf32(float f) {
    uint32_t r;
    asm("cvt.rna.tf32.f32 %0, %1;" : "=r"(r) : "f"(f));
    return r;
}
__device__ __forceinline__ void cp_async16(uint32_t dst, const void* src) {
    asm volatile("cp.async.cg.shared.global [%0], [%1], 16;" :: "r"(dst), "l"(src) : "memory");
}

// ---------------- 0: dtype-detect + convert (packed int2) + histogram + attn scalars ----------------
// int64 detection: ids < 50000 so high 32-bit words are 0; if int32, the odd
// words are 64 random ids (all-zero prob ~ (1/50000)^64 ~ 0).
__global__ void k_convert(const void* __restrict__ ei, const float* __restrict__ x,
                          const float* __restrict__ Wa, const float* __restrict__ as_,
                          const float* __restrict__ ad_) {
    __shared__ int s_is64;
    __shared__ float sva[FDIM], svb[FDIM];
    const unsigned int* w = (const unsigned int*)ei;
    int gid = blockIdx.x * blockDim.x + threadIdx.x;

    if (threadIdx.x == 0) {
        int z = 1;
        for (int i = 0; i < 64; i++) if (w[2 * i + 1] != 0u) { z = 0; break; }
        s_is64 = z;
    }
    if (blockIdx.x * blockDim.x < N_NODES) {
        if (threadIdx.x < FDIM) {
            int k = threadIdx.x;
            float va = 0.f, vb = 0.f;
            #pragma unroll 8
            for (int j = 0; j < FDIM; j++) {
                float wv = Wa[k * FDIM + j];
                va = fmaf(wv, as_[j], va);
                vb = fmaf(wv, ad_[j], vb);
            }
            sva[k] = va;
            svb[k] = vb;
        }
        __syncthreads();
        if (gid < N_NODES) {
            const float4* xr = (const float4*)(x + (size_t)gid * FDIM);
            float ss = 0.f, sd = 0.f;
            #pragma unroll
            for (int i = 0; i < FDIM / 4; i++) {
                float4 v = xr[i];
                ss = fmaf(v.x, sva[4*i], fmaf(v.y, sva[4*i+1], fmaf(v.z, sva[4*i+2], fmaf(v.w, sva[4*i+3], ss))));
                sd = fmaf(v.x, svb[4*i], fmaf(v.y, svb[4*i+1], fmaf(v.z, svb[4*i+2], fmaf(v.w, svb[4*i+3], sd))));
            }
            g_sd[gid].x = ss;
            g_sdst[gid] = sd;
        }
    } else {
        __syncthreads();
    }
    int is64 = s_is64;
    int stride = gridDim.x * blockDim.x;
    for (int i = gid; i < N_EDGES; i += stride) {
        int s, d;
        if (is64) {
            s = (int)((const long long*)ei)[i];
            d = (int)((const long long*)ei)[N_EDGES + i];
        } else {
            s = ((const int*)ei)[i];
            d = ((const int*)ei)[N_EDGES + i];
        }
        g_edge[i] = make_int2(s, d);
        atomicAdd(&g_cnt[d], 1);
    }
}

// ---------------- 1: row-slice assignment (block scan + 1 atomic per block) ----------------
__global__ void k_rowassign() {
    __shared__ int s_warp[8];
    __shared__ int s_base;
    int tid = threadIdx.x;
    int n = blockIdx.x * 256 + tid;
    int lane = tid & 31, wid = tid >> 5;
    int c = (n < N_NODES) ? g_cnt[n] : 0;
    int v = c;
    #pragma unroll
    for (int off = 1; off < 32; off <<= 1) {
        int u = __shfl_up_sync(0xffffffffu, v, off);
        if (lane >= off) v += u;
    }
    if (lane == 31) s_warp[wid] = v;
    __syncthreads();
    if (tid < 8) {
        int pv = s_warp[tid];
        #pragma unroll
        for (int off = 1; off < 8; off <<= 1) {
            int u = __shfl_up_sync(0xffu, pv, off);
            if (tid >= off) pv += u;
        }
        s_warp[tid] = pv;
        if (tid == 7) s_base = atomicAdd(&g_cnt[N_NODES], pv);
    }
    __syncthreads();
    int excl = v - c + (wid > 0 ? s_warp[wid - 1] : 0);
    if (n < N_NODES) {
        g_row[n] = s_base + excl;
        g_cur[n] = 0;
        g_sd[n].y = rsqrtf((float)c + 1.0f);
    }
}

// ---------------- 2: scatter src into CSR (packed edge read) ----------------
__global__ void k_scatter() {
    int stride = gridDim.x * blockDim.x;
    for (int e = blockIdx.x * blockDim.x + threadIdx.x; e < N_EDGES; e += stride) {
        int2 ed = g_edge[e];
        int pos = g_row[ed.y] + atomicAdd(&g_cur[ed.y], 1);
        g_csrc[pos] = ed.x;
    }
}

// ---------------- 3: warp-per-node aggregation — guard-free unroll x2 (MLP 2) ----------------
// Padded lanes (>= m) carry zero weights; their gathers hit x[0] with weight 0,
// and the plain sum uses ws = (we != 0) as exact validity (real we >= exp(-1.2)).
__global__ void __launch_bounds__(256) k_agg(const float* __restrict__ x) {
    int wid = (blockIdx.x * blockDim.x + threadIdx.x) >> 5;
    int lane = threadIdx.x & 31;
    if (wid >= N_NODES) return;
    int d = wid;
    int row = g_row[d], end = row + g_cnt[d];
    float sd = g_sdst[d];
    float2 dsd = g_sd[d];
    float dvd = dsd.y;
    int q = lane & 15, half = lane >> 4;
    const float4* x4 = (const float4*)x;

    float4 aG = make_float4(0.f, 0.f, 0.f, 0.f);
    float4 aA = aG, aS = aG;
    float denom = 0.f;

    for (int base = row; base < end; base += 32) {
        int m = min(32, end - base);
        int   s_r = 0;
        float we_r = 0.f, wg_r = 0.f;
        if (lane < m) {
            s_r = g_csrc[base + lane];
            float2 sv = g_sd[s_r];
            we_r = expf(lrelu(sv.x + sd));
            wg_r = sv.y * dvd;
            denom += we_r;
        }
        // i2 max is 28, so shfl source lanes (i2+half, i2+2+half) stay <= 31.
        for (int i2 = 0; i2 < m; i2 += 4) {
            int   sA  = __shfl_sync(0xffffffffu, s_r,  i2 + half);
            float weA = __shfl_sync(0xffffffffu, we_r, i2 + half);
            float wgA = __shfl_sync(0xffffffffu, wg_r, i2 + half);
            int   sB  = __shfl_sync(0xffffffffu, s_r,  i2 + 2 + half);
            float weB = __shfl_sync(0xffffffffu, we_r, i2 + 2 + half);
            float wgB = __shfl_sync(0xffffffffu, wg_r, i2 + 2 + half);
            float4 xvA = x4[sA * 16 + q];      // two independent gathers -> MLP 2
            float4 xvB = x4[sB * 16 + q];
            float wsA = (weA != 0.f) ? 1.f : 0.f;
            float wsB = (weB != 0.f) ? 1.f : 0.f;
            aG.x = fmaf(wgA, xvA.x, aG.x); aG.y = fmaf(wgA, xvA.y, aG.y);
            aG.z = fmaf(wgA, xvA.z, aG.z); aG.w = fmaf(wgA, xvA.w, aG.w);
            aA.x = fmaf(weA, xvA.x, aA.x); aA.y = fmaf(weA, xvA.y, aA.y);
            aA.z = fmaf(weA, xvA.z, aA.z); aA.w = fmaf(weA, xvA.w, aA.w);
            aS.x = fmaf(wsA, xvA.x, aS.x); aS.y = fmaf(wsA, xvA.y, aS.y);
            aS.z = fmaf(wsA, xvA.z, aS.z); aS.w = fmaf(wsA, xvA.w, aS.w);
            aG.x = fmaf(wgB, xvB.x, aG.x); aG.y = fmaf(wgB, xvB.y, aG.y);
            aG.z = fmaf(wgB, xvB.z, aG.z); aG.w = fmaf(wgB, xvB.w, aG.w);
            aA.x = fmaf(weB, xvB.x, aA.x); aA.y = fmaf(weB, xvB.y, aA.y);
            aA.z = fmaf(weB, xvB.z, aA.z); aA.w = fmaf(weB, xvB.w, aA.w);
            aS.x = fmaf(wsB, xvB.x, aS.x); aS.y = fmaf(wsB, xvB.y, aS.y);
            aS.z = fmaf(wsB, xvB.z, aS.z); aS.w = fmaf(wsB, xvB.w, aS.w);
        }
    }

    #pragma unroll
    for (int off = 16; off > 0; off >>= 1)
        denom += __shfl_xor_sync(0xffffffffu, denom, off);
    float selfexp = expf(lrelu(dsd.x + sd));
    float rdenom = 1.0f / (denom + selfexp);

    #pragma unroll
    for (int c = 0; c < 12; c++) {
        float* p = (c < 4) ? (&aG.x + c) : (c < 8) ? (&aA.x + (c - 4)) : (&aS.x + (c - 8));
        *p += __shfl_xor_sync(0xffffffffu, *p, 16);
    }
    if (half == 0) {
        float4 xd = x4[d * 16 + q];
        float wd = dvd * dvd;
        float4 G = make_float4(fmaf(wd, xd.x, aG.x), fmaf(wd, xd.y, aG.y),
                               fmaf(wd, xd.z, aG.z), fmaf(wd, xd.w, aG.w));
        float4 A = make_float4((aA.x + selfexp * xd.x) * rdenom, (aA.y + selfexp * xd.y) * rdenom,
                               (aA.z + selfexp * xd.z) * rdenom, (aA.w + selfexp * xd.w) * rdenom);
        ((float4*)g_aggG)[d * 16 + q] = G;
        ((float4*)g_aggA)[d * 16 + q] = A;
        ((float4*)g_aggS)[d * 16 + q] = aS;
    }
}

// ---------------- 4: tensor-core k_final, cp.async double-buffered (R15, measured) ----------------
// 768 thr = 24 warps = 6 panels x 4 N-quarters(16).
// panels: 0 aggG@Wg  1 aggA@Wa  2 aggS@Wl  3 aggS@Wi  4 x@Wr  5 x@Wi
// epilogue: SAGE = ci*P2 + P4 + bl ; GIN = P3 + P5 + bi
#define PSZ 2176                       // 32*68
#define UBUF 8704                      // 4*2176
#define KT_SMEM_FLOATS (17408 + 13056 + 256 + 256 + 32)
#define KT_SMEM_BYTES (KT_SMEM_FLOATS * 4)

__global__ void __launch_bounds__(768, 1) k_final_tc(
        const float* __restrict__ x,
        const float* __restrict__ Wg, const float* __restrict__ bg,
        const float* __restrict__ Wa, const float* __restrict__ ba,
        const float* __restrict__ Wl, const float* __restrict__ bl,
        const float* __restrict__ Wr,
        const float* __restrict__ Wi, const float* __restrict__ bi,
        const float* __restrict__ Wo, const float* __restrict__ bo,
        float* __restrict__ out) {
    extern __shared__ float sm[];
    float* sU   = sm;
    float* sP   = sm + 17408;
    float* sWo  = sm + 30464;
    float* sBia = sm + 30720;
    float* sCi  = sm + 30976;
    int tid = threadIdx.x;
    int wwid = tid >> 5, lane = tid & 31;
    int p = wwid >> 2, nq = wwid & 3;
    int lg = lane >> 2, lt = lane & 3;
    uint32_t sU_u32 = (uint32_t)__cvta_generic_to_shared(sU);

    const float4* gsrc[4] = { (const float4*)g_aggG, (const float4*)g_aggA,
                              (const float4*)g_aggS, (const float4*)x };

    // prefetch tile 0 into buffer 0
    {
        int base = blockIdx.x * 32;
        for (int idx = tid; idx < 2048; idx += 768) {
            int a = idx >> 9, rem = idx & 511;
            int nl = rem & 31, kq = rem >> 5;
            int nn = min(base + nl, N_NODES - 1);
            cp_async16(sU_u32 + (a * PSZ + nl * 68 + kq * 4) * 4, gsrc[a] + nn * 16 + kq);
        }
        asm volatile("cp.async.commit_group;" ::: "memory");
    }

    if (tid < 256) sWo[tid] = Wo[tid];
    if (tid < 64) {
        sBia[tid] = bg[tid]; sBia[64 + tid] = ba[tid];
        sBia[128 + tid] = bl[tid]; sBia[192 + tid] = bi[tid];
    }
    float bout = bo[0];

    const float* Wsrc = (p == 0) ? Wg : (p == 1) ? Wa : (p == 2) ? Wl
                      : (p == 3) ? Wi : (p == 4) ? Wr : Wi;
    uint32_t bf[8][2][2];
    #pragma unroll
    for (int kc = 0; kc < 8; kc++)
        #pragma unroll
        for (int nc = 0; nc < 2; nc++) {
            int n = nq * 16 + nc * 8 + lg;
            int k0 = kc * 8 + lt;
            bf[kc][nc][0] = f2tf32(Wsrc[k0 * 64 + n]);
            bf[kc][nc][1] = f2tf32(Wsrc[(k0 + 4) * 64 + n]);
        }

    int ain = (p <= 1) ? p : (p <= 3) ? 2 : 3;
    int buf = 0;
    for (int tile = blockIdx.x; tile < N_TILES; tile += gridDim.x) {
        int base = tile * 32;
        int nxt = tile + gridDim.x;
        if (nxt < N_TILES) {
            int nbase = nxt * 32;
            int noff = (buf ^ 1) * UBUF;
            for (int idx = tid; idx < 2048; idx += 768) {
                int a = idx >> 9, rem = idx & 511;
                int nl = rem & 31, kq = rem >> 5;
                int nn = min(nbase + nl, N_NODES - 1);
                cp_async16(sU_u32 + (noff + a * PSZ + nl * 68 + kq * 4) * 4,
                           gsrc[a] + nn * 16 + kq);
            }
            asm volatile("cp.async.commit_group;" ::: "memory");
            asm volatile("cp.async.wait_group 1;" ::: "memory");
        } else {
            asm volatile("cp.async.wait_group 0;" ::: "memory");
        }
        __syncthreads();

        if (tid < 32) {
            int n = base + tid;
            sCi[tid] = (n < N_NODES) ? 1.0f / fmaxf((float)g_cnt[n], 1.0f) : 0.f;
        }

        const float* sUp = sU + buf * UBUF + ain * PSZ;
        float* sPp = sP + p * PSZ;
        #pragma unroll
        for (int mc = 0; mc < 2; mc++) {
            float c0[4] = {0.f, 0.f, 0.f, 0.f};
            float c1[4] = {0.f, 0.f, 0.f, 0.f};
            int row = mc * 16 + lg;
            #pragma unroll
            for (int kc = 0; kc < 8; kc++) {
                uint32_t af[4];
                int col = kc * 8 + lt;
                af[0] = __float_as_uint(sUp[row * 68 + col]);
                af[1] = __float_as_uint(sUp[(row + 8) * 68 + col]);
                af[2] = __float_as_uint(sUp[row * 68 + col + 4]);
                af[3] = __float_as_uint(sUp[(row + 8) * 68 + col + 4]);
                mma_tf32(c0, af, bf[kc][0]);
                mma_tf32(c1, af, bf[kc][1]);
            }
            #pragma unroll
            for (int nc = 0; nc < 2; nc++) {
                float* c = (nc == 0) ? c0 : c1;
                int node = mc * 16 + lg;
                int jg = nq * 16 + nc * 8 + 2 * lt;
                sPp[node * 68 + jg] = c[0];
                sPp[node * 68 + jg + 1] = c[1];
                sPp[(node + 8) * 68 + jg] = c[2];
                sPp[(node + 8) * 68 + jg + 1] = c[3];
            }
        }
        __syncthreads();

        if (tid < 512) {
            int nl = tid >> 4, jb = tid & 15;
            int n = base + nl;
            float ci = sCi[nl];
            float z = 0.f;
            #pragma unroll
            for (int jj = 0; jj < 4; jj++) {
                int j = jb * 4 + jj;
                float vg = sP[0 * PSZ + nl * 68 + j] + sBia[j];
                float va2 = sP[1 * PSZ + nl * 68 + j] + sBia[64 + j];
                float vs = fmaf(ci, sP[2 * PSZ + nl * 68 + j], sP[4 * PSZ + nl * 68 + j]) + sBia[128 + j];
                float vi = sP[3 * PSZ + nl * 68 + j] + sP[5 * PSZ + nl * 68 + j] + sBia[192 + j];
                z += fmaxf(vg, 0.f) * sWo[j] + fmaxf(va2, 0.f) * sWo[64 + j]
                   + fmaxf(vs, 0.f) * sWo[128 + j] + fmaxf(vi, 0.f) * sWo[192 + j];
            }
            z += __shfl_down_sync(0xffffffffu, z, 8, 16);
            z += __shfl_down_sync(0xffffffffu, z, 4, 16);
            z += __shfl_down_sync(0xffffffffu, z, 2, 16);
            z += __shfl_down_sync(0xffffffffu, z, 1, 16);
            if (jb == 0 && n < N_NODES)
                out[n] = 1.0f / (1.0f + expf(-(z + bout)));
        }
        __syncthreads();
        buf ^= 1;
    }
}

// ---------------- launch ----------------
extern "C" void kernel_launch(void* const* d_in, const int* in_sizes, int n_in,
                              void* d_out, int out_size) {
    const float* x    = (const float*)d_in[0];
    const void*  ei   = d_in[1];
    const float* Wg   = (const float*)d_in[2];
    const float* bg   = (const float*)d_in[3];
    const float* Wa   = (const float*)d_in[4];
    const float* asrc = (const float*)d_in[5];
    const float* adst = (const float*)d_in[6];
    const float* ba   = (const float*)d_in[7];
    const float* Wl   = (const float*)d_in[8];
    const float* bl   = (const float*)d_in[9];
    const float* Wr   = (const float*)d_in[10];
    const float* Wi   = (const float*)d_in[11];
    const float* bi   = (const float*)d_in[12];
    const float* Wo   = (const float*)d_in[13];
    const float* bo   = (const float*)d_in[14];
    float* out = (float*)d_out;

    cudaFuncSetAttribute(k_final_tc, cudaFuncAttributeMaxDynamicSharedMemorySize, KT_SMEM_BYTES);

    void* cnt_ptr = nullptr;
    cudaGetSymbolAddress(&cnt_ptr, g_cnt);
    cudaMemsetAsync(cnt_ptr, 0, (N_NODES + 1) * sizeof(int), 0);

    k_convert<<<2048, 256>>>(ei, x, Wa, asrc, adst);                       // 0
    k_rowassign<<<(N_NODES + 255) / 256, 256>>>();                         // 1
    k_scatter<<<1024, 256>>>();                                            // 2
    k_agg<<<(N_NODES * 32 + 255) / 256, 256>>>(x);                         // 3 (profiled)
    k_final_tc<<<148, 768, KT_SMEM_BYTES>>>(x, Wg, bg, Wa, ba, Wl, bl,     // 4
                                            Wr, Wi, bi, Wo, bo, out);
}

// round 17
// speedup vs baseline: 2.3265x; 1.0766x over previous
#include <cuda_runtime.h>
#include <cstdint>

#define N_NODES 50000
#define N_EDGES 800000
#define FDIM 64
#define N_TILES ((N_NODES + 31) / 32)   // 1563

// ---------------- device scratch ----------------
__device__ __align__(8) int2 g_edge[N_EDGES];   // packed (src, dst)
__device__ int   g_csrc[N_EDGES];          // CSR: src ids grouped by dst
__device__ int   g_row[N_NODES];           // CSR slice start per dst (arbitrary order)
__device__ int   g_cnt[N_NODES + 1];       // in-degree histogram; [N] = global offset counter
__device__ int   g_cur[N_NODES];           // scatter cursors
__device__ __align__(16) float g_aggG[N_NODES * FDIM];
__device__ __align__(16) float g_aggA[N_NODES * FDIM];
__device__ __align__(16) float g_aggS[N_NODES * FDIM];
__device__ __align__(16) float g_aggM[N_NODES * FDIM];   // mean = aggS / max(deg,1)
__device__ __align__(8)  float2 g_sd[N_NODES];   // {ssrc, dinv} packed for 1-LDG edge gather
__device__ float g_sdst[N_NODES];

__device__ __forceinline__ float lrelu(float v) { return v > 0.f ? v : 0.2f * v; }

__device__ __forceinline__ void mma_tf32(float c[4], const uint32_t a[4], const uint32_t b[2]) {
    asm("mma.sync.aligned.m16n8k8.row.col.f32.tf32.tf32.f32 "
        "{%0,%1,%2,%3},{%4,%5,%6,%7},{%8,%9},{%0,%1,%2,%3};"
        : "+f"(c[0]), "+f"(c[1]), "+f"(c[2]), "+f"(c[3])
        : "r"(a[0]), "r"(a[1]), "r"(a[2]), "r"(a[3]), "r"(b[0]), "r"(b[1]));
}
__device__ __forceinline__ uint32_t f2tf32(float f) {
    uint32_t r;
    asm("cvt.rna.tf32.f32 %0, %1;" : "=r"(r) : "f"(f));
    return r;
}
__device__ __forceinline__ void cp_async16(uint32_t dst, const void* src) {
    asm volatile("cp.async.cg.shared.global [%0], [%1], 16;" :: "r"(dst), "l"(src) : "memory");
}

// ---------------- 0: dtype-detect + convert (packed int2) + histogram + attn scalars ----------------
// int64 detection: ids < 50000 so high 32-bit words are 0; if int32, the odd
// words are 64 random ids (all-zero prob ~ (1/50000)^64 ~ 0).
__global__ void k_convert(const void* __restrict__ ei, const float* __restrict__ x,
                          const float* __restrict__ Wa, const float* __restrict__ as_,
                          const float* __restrict__ ad_) {
    __shared__ int s_is64;
    __shared__ float sva[FDIM], svb[FDIM];
    const unsigned int* w = (const unsigned int*)ei;
    int gid = blockIdx.x * blockDim.x + threadIdx.x;

    if (threadIdx.x == 0) {
        int z = 1;
        for (int i = 0; i < 64; i++) if (w[2 * i + 1] != 0u) { z = 0; break; }
        s_is64 = z;
    }
    if (blockIdx.x * blockDim.x < N_NODES) {
        if (threadIdx.x < FDIM) {
            int k = threadIdx.x;
            float va = 0.f, vb = 0.f;
            #pragma unroll 8
            for (int j = 0; j < FDIM; j++) {
                float wv = Wa[k * FDIM + j];
                va = fmaf(wv, as_[j], va);
                vb = fmaf(wv, ad_[j], vb);
            }
            sva[k] = va;
            svb[k] = vb;
        }
        __syncthreads();
        if (gid < N_NODES) {
            const float4* xr = (const float4*)(x + (size_t)gid * FDIM);
            float ss = 0.f, sd = 0.f;
            #pragma unroll
            for (int i = 0; i < FDIM / 4; i++) {
                float4 v = xr[i];
                ss = fmaf(v.x, sva[4*i], fmaf(v.y, sva[4*i+1], fmaf(v.z, sva[4*i+2], fmaf(v.w, sva[4*i+3], ss))));
                sd = fmaf(v.x, svb[4*i], fmaf(v.y, svb[4*i+1], fmaf(v.z, svb[4*i+2], fmaf(v.w, svb[4*i+3], sd))));
            }
            g_sd[gid].x = ss;
            g_sdst[gid] = sd;
        }
    } else {
        __syncthreads();
    }
    int is64 = s_is64;
    int stride = gridDim.x * blockDim.x;
    for (int i = gid; i < N_EDGES; i += stride) {
        int s, d;
        if (is64) {
            s = (int)((const long long*)ei)[i];
            d = (int)((const long long*)ei)[N_EDGES + i];
        } else {
            s = ((const int*)ei)[i];
            d = ((const int*)ei)[N_EDGES + i];
        }
        g_edge[i] = make_int2(s, d);
        atomicAdd(&g_cnt[d], 1);
    }
}

// ---------------- 1: row-slice assignment (block scan + 1 atomic per block) ----------------
__global__ void k_rowassign() {
    __shared__ int s_warp[8];
    __shared__ int s_base;
    int tid = threadIdx.x;
    int n = blockIdx.x * 256 + tid;
    int lane = tid & 31, wid = tid >> 5;
    int c = (n < N_NODES) ? g_cnt[n] : 0;
    int v = c;
    #pragma unroll
    for (int off = 1; off < 32; off <<= 1) {
        int u = __shfl_up_sync(0xffffffffu, v, off);
        if (lane >= off) v += u;
    }
    if (lane == 31) s_warp[wid] = v;
    __syncthreads();
    if (tid < 8) {
        int pv = s_warp[tid];
        #pragma unroll
        for (int off = 1; off < 8; off <<= 1) {
            int u = __shfl_up_sync(0xffu, pv, off);
            if (tid >= off) pv += u;
        }
        s_warp[tid] = pv;
        if (tid == 7) s_base = atomicAdd(&g_cnt[N_NODES], pv);
    }
    __syncthreads();
    int excl = v - c + (wid > 0 ? s_warp[wid - 1] : 0);
    if (n < N_NODES) {
        g_row[n] = s_base + excl;
        g_cur[n] = 0;
        g_sd[n].y = rsqrtf((float)c + 1.0f);
    }
}

// ---------------- 2: scatter src into CSR (packed edge read) ----------------
__global__ void k_scatter() {
    int stride = gridDim.x * blockDim.x;
    for (int e = blockIdx.x * blockDim.x + threadIdx.x; e < N_EDGES; e += stride) {
        int2 ed = g_edge[e];
        int pos = g_row[ed.y] + atomicAdd(&g_cur[ed.y], 1);
        g_csrc[pos] = ed.x;
    }
}

// ---------------- 3: warp-per-node aggregation (R16 + mean output) ----------------
__global__ void __launch_bounds__(256) k_agg(const float* __restrict__ x) {
    int wid = (blockIdx.x * blockDim.x + threadIdx.x) >> 5;
    int lane = threadIdx.x & 31;
    if (wid >= N_NODES) return;
    int d = wid;
    int row = g_row[d], end = row + g_cnt[d];
    float sd = g_sdst[d];
    float2 dsd = g_sd[d];
    float dvd = dsd.y;
    int q = lane & 15, half = lane >> 4;
    const float4* x4 = (const float4*)x;

    float4 aG = make_float4(0.f, 0.f, 0.f, 0.f);
    float4 aA = aG, aS = aG;
    float denom = 0.f;

    for (int base = row; base < end; base += 32) {
        int m = min(32, end - base);
        int   s_r = 0;
        float we_r = 0.f, wg_r = 0.f;
        if (lane < m) {
            s_r = g_csrc[base + lane];
            float2 sv = g_sd[s_r];
            we_r = expf(lrelu(sv.x + sd));
            wg_r = sv.y * dvd;
            denom += we_r;
        }
        for (int i2 = 0; i2 < m; i2 += 4) {
            int   sA  = __shfl_sync(0xffffffffu, s_r,  i2 + half);
            float weA = __shfl_sync(0xffffffffu, we_r, i2 + half);
            float wgA = __shfl_sync(0xffffffffu, wg_r, i2 + half);
            int   sB  = __shfl_sync(0xffffffffu, s_r,  i2 + 2 + half);
            float weB = __shfl_sync(0xffffffffu, we_r, i2 + 2 + half);
            float wgB = __shfl_sync(0xffffffffu, wg_r, i2 + 2 + half);
            float4 xvA = x4[sA * 16 + q];
            float4 xvB = x4[sB * 16 + q];
            float wsA = (weA != 0.f) ? 1.f : 0.f;
            float wsB = (weB != 0.f) ? 1.f : 0.f;
            aG.x = fmaf(wgA, xvA.x, aG.x); aG.y = fmaf(wgA, xvA.y, aG.y);
            aG.z = fmaf(wgA, xvA.z, aG.z); aG.w = fmaf(wgA, xvA.w, aG.w);
            aA.x = fmaf(weA, xvA.x, aA.x); aA.y = fmaf(weA, xvA.y, aA.y);
            aA.z = fmaf(weA, xvA.z, aA.z); aA.w = fmaf(weA, xvA.w, aA.w);
            aS.x = fmaf(wsA, xvA.x, aS.x); aS.y = fmaf(wsA, xvA.y, aS.y);
            aS.z = fmaf(wsA, xvA.z, aS.z); aS.w = fmaf(wsA, xvA.w, aS.w);
            aG.x = fmaf(wgB, xvB.x, aG.x); aG.y = fmaf(wgB, xvB.y, aG.y);
            aG.z = fmaf(wgB, xvB.z, aG.z); aG.w = fmaf(wgB, xvB.w, aG.w);
            aA.x = fmaf(weB, xvB.x, aA.x); aA.y = fmaf(weB, xvB.y, aA.y);
            aA.z = fmaf(weB, xvB.z, aA.z); aA.w = fmaf(weB, xvB.w, aA.w);
            aS.x = fmaf(wsB, xvB.x, aS.x); aS.y = fmaf(wsB, xvB.y, aS.y);
            aS.z = fmaf(wsB, xvB.z, aS.z); aS.w = fmaf(wsB, xvB.w, aS.w);
        }
    }

    #pragma unroll
    for (int off = 16; off > 0; off >>= 1)
        denom += __shfl_xor_sync(0xffffffffu, denom, off);
    float selfexp = expf(lrelu(dsd.x + sd));
    float rdenom = 1.0f / (denom + selfexp);

    #pragma unroll
    for (int c = 0; c < 12; c++) {
        float* p = (c < 4) ? (&aG.x + c) : (c < 8) ? (&aA.x + (c - 4)) : (&aS.x + (c - 8));
        *p += __shfl_xor_sync(0xffffffffu, *p, 16);
    }
    if (half == 0) {
        float4 xd = x4[d * 16 + q];
        float wd = dvd * dvd;
        float4 G = make_float4(fmaf(wd, xd.x, aG.x), fmaf(wd, xd.y, aG.y),
                               fmaf(wd, xd.z, aG.z), fmaf(wd, xd.w, aG.w));
        float4 A = make_float4((aA.x + selfexp * xd.x) * rdenom, (aA.y + selfexp * xd.y) * rdenom,
                               (aA.z + selfexp * xd.z) * rdenom, (aA.w + selfexp * xd.w) * rdenom);
        float ci = 1.0f / fmaxf((float)(end - row), 1.0f);
        ((float4*)g_aggG)[d * 16 + q] = G;
        ((float4*)g_aggA)[d * 16 + q] = A;
        ((float4*)g_aggS)[d * 16 + q] = aS;
        ((float4*)g_aggM)[d * 16 + q] =
            make_float4(aS.x * ci, aS.y * ci, aS.z * ci, aS.w * ci);
    }
}

// ---------------- 4: tensor-core k_final — branch-complete panels, in-register epilogue ----------------
// 512 thr = 16 warps = 4 branch panels x 4 N-quarters(16).
// panels: 0 GCN: aggG@Wg (K=64)   1 GAT: aggA@Wa (K=64)
//         2 SAGE: [aggM|x]@[Wl;Wr] (K=128)   3 GIN: [aggS|x]@[Wi;Wi] (K=128)
// Every C fragment is a COMPLETE branch h -> relu/bias/Wout applied in registers,
// 2 shfls + tiny zbuf replace the old 51KB sP + conflicted scalar reads.
// staged arrays (cp.async raw f32): 0 aggG 1 aggA 2 aggM 3 aggS 4 x
// smem floats: sU[2][5][2176] @0 (21760) | sZ[16][32] @21760 (512)
#define PSZ 2176                       // 32*68
#define UBUF 10880                     // 5*2176
#define KT_SMEM_FLOATS (21760 + 512)
#define KT_SMEM_BYTES (KT_SMEM_FLOATS * 4)

__global__ void __launch_bounds__(512, 1) k_final_tc(
        const float* __restrict__ x,
        const float* __restrict__ Wg, const float* __restrict__ bg,
        const float* __restrict__ Wa, const float* __restrict__ ba,
        const float* __restrict__ Wl, const float* __restrict__ bl,
        const float* __restrict__ Wr,
        const float* __restrict__ Wi, const float* __restrict__ bi,
        const float* __restrict__ Wo, const float* __restrict__ bo,
        float* __restrict__ out) {
    extern __shared__ float sm[];
    float* sU = sm;
    float* sZ = sm + 21760;
    int tid = threadIdx.x;
    int wwid = tid >> 5, lane = tid & 31;
    int p = wwid >> 2, nq = wwid & 3;
    int lg = lane >> 2, lt = lane & 3;
    uint32_t sU_u32 = (uint32_t)__cvta_generic_to_shared(sU);

    const float4* gsrc[5] = { (const float4*)g_aggG, (const float4*)g_aggA,
                              (const float4*)g_aggM, (const float4*)g_aggS,
                              (const float4*)x };

    // prefetch tile 0 into buffer 0
    {
        int base = blockIdx.x * 32;
        for (int idx = tid; idx < 2560; idx += 512) {
            int a = idx >> 9, rem = idx & 511;
            int nl = rem & 31, kq = rem >> 5;
            int nn = min(base + nl, N_NODES - 1);
            cp_async16(sU_u32 + (a * PSZ + nl * 68 + kq * 4) * 4, gsrc[a] + nn * 16 + kq);
        }
        asm volatile("cp.async.commit_group;" ::: "memory");
    }

    // per-lane epilogue constants (branch = p)
    const float* bsrc = (p == 0) ? bg : (p == 1) ? ba : (p == 2) ? bl : bi;
    int jg0 = nq * 16 + 2 * lt;
    int jg1 = jg0 + 8;
    float woA = Wo[p * 64 + jg0], woB = Wo[p * 64 + jg0 + 1];
    float woC = Wo[p * 64 + jg1], woD = Wo[p * 64 + jg1 + 1];
    float bA = bsrc[jg0], bB = bsrc[jg0 + 1], bC = bsrc[jg1], bD = bsrc[jg1 + 1];
    float bout = bo[0];

    // B fragments: K-chunks 0..7 from WA, 8..15 (p>=2) from WB
    const float* WA = (p == 0) ? Wg : (p == 1) ? Wa : (p == 2) ? Wl : Wi;
    const float* WB = (p == 2) ? Wr : Wi;
    uint32_t bf[16][2][2];
    #pragma unroll
    for (int kc = 0; kc < 8; kc++)
        #pragma unroll
        for (int nc = 0; nc < 2; nc++) {
            int n = nq * 16 + nc * 8 + lg;
            int k0 = kc * 8 + lt;
            bf[kc][nc][0] = f2tf32(WA[k0 * 64 + n]);
            bf[kc][nc][1] = f2tf32(WA[(k0 + 4) * 64 + n]);
        }
    if (p >= 2) {
        #pragma unroll
        for (int kc = 8; kc < 16; kc++)
            #pragma unroll
            for (int nc = 0; nc < 2; nc++) {
                int n = nq * 16 + nc * 8 + lg;
                int k0 = (kc - 8) * 8 + lt;
                bf[kc][nc][0] = f2tf32(WB[k0 * 64 + n]);
                bf[kc][nc][1] = f2tf32(WB[(k0 + 4) * 64 + n]);
            }
    }

    int arrA = p;                     // panel's primary input array
    int buf = 0;
    for (int tile = blockIdx.x; tile < N_TILES; tile += gridDim.x) {
        int base = tile * 32;
        int nxt = tile + gridDim.x;
        if (nxt < N_TILES) {
            int nbase = nxt * 32;
            int noff = (buf ^ 1) * UBUF;
            for (int idx = tid; idx < 2560; idx += 512) {
                int a = idx >> 9, rem = idx & 511;
                int nl = rem & 31, kq = rem >> 5;
                int nn = min(nbase + nl, N_NODES - 1);
                cp_async16(sU_u32 + (noff + a * PSZ + nl * 68 + kq * 4) * 4,
                           gsrc[a] + nn * 16 + kq);
            }
            asm volatile("cp.async.commit_group;" ::: "memory");
            asm volatile("cp.async.wait_group 1;" ::: "memory");
        } else {
            asm volatile("cp.async.wait_group 0;" ::: "memory");
        }
        __syncthreads();               // buf ready; prev tile's sZ fully consumed

        const float* uA = sU + buf * UBUF + arrA * PSZ;
        const float* uB = sU + buf * UBUF + 4 * PSZ;
        float zacc[4];
        #pragma unroll
        for (int mc = 0; mc < 2; mc++) {
            float c0[4] = {0.f, 0.f, 0.f, 0.f};
            float c1[4] = {0.f, 0.f, 0.f, 0.f};
            int row = mc * 16 + lg;
            #pragma unroll
            for (int kc = 0; kc < 8; kc++) {
                uint32_t af[4];
                int col = kc * 8 + lt;
                af[0] = __float_as_uint(uA[row * 68 + col]);
                af[1] = __float_as_uint(uA[(row + 8) * 68 + col]);
                af[2] = __float_as_uint(uA[row * 68 + col + 4]);
                af[3] = __float_as_uint(uA[(row + 8) * 68 + col + 4]);
                mma_tf32(c0, af, bf[kc][0]);
                mma_tf32(c1, af, bf[kc][1]);
            }
            if (p >= 2) {
                #pragma unroll
                for (int kc = 8; kc < 16; kc++) {
                    uint32_t af[4];
                    int col = (kc - 8) * 8 + lt;
                    af[0] = __float_as_uint(uB[row * 68 + col]);
                    af[1] = __float_as_uint(uB[(row + 8) * 68 + col]);
                    af[2] = __float_as_uint(uB[row * 68 + col + 4]);
                    af[3] = __float_as_uint(uB[(row + 8) * 68 + col + 4]);
                    mma_tf32(c0, af, bf[kc][0]);
                    mma_tf32(c1, af, bf[kc][1]);
                }
            }
            // in-register branch epilogue: relu(h+bias)*wo summed over this lane's 4 j
            zacc[mc * 2] =
                  fmaxf(c0[0] + bA, 0.f) * woA + fmaxf(c0[1] + bB, 0.f) * woB
                + fmaxf(c1[0] + bC, 0.f) * woC + fmaxf(c1[1] + bD, 0.f) * woD;
            zacc[mc * 2 + 1] =
                  fmaxf(c0[2] + bA, 0.f) * woA + fmaxf(c0[3] + bB, 0.f) * woB
                + fmaxf(c1[2] + bC, 0.f) * woC + fmaxf(c1[3] + bD, 0.f) * woD;
        }
        #pragma unroll
        for (int k = 0; k < 4; k++) {
            zacc[k] += __shfl_xor_sync(0xffffffffu, zacc[k], 1);
            zacc[k] += __shfl_xor_sync(0xffffffffu, zacc[k], 2);
        }
        if (lt == 0) {
            sZ[wwid * 32 + lg]      = zacc[0];
            sZ[wwid * 32 + lg + 8]  = zacc[1];
            sZ[wwid * 32 + lg + 16] = zacc[2];
            sZ[wwid * 32 + lg + 24] = zacc[3];
        }
        __syncthreads();               // sZ complete
        if (tid < 32) {
            float z = bout;
            #pragma unroll
            for (int w2 = 0; w2 < 16; w2++) z += sZ[w2 * 32 + tid];
            int n = base + tid;
            if (n < N_NODES) out[n] = 1.0f / (1.0f + expf(-z));
        }
        buf ^= 1;
    }
}

// ---------------- launch ----------------
extern "C" void kernel_launch(void* const* d_in, const int* in_sizes, int n_in,
                              void* d_out, int out_size) {
    const float* x    = (const float*)d_in[0];
    const void*  ei   = d_in[1];
    const float* Wg   = (const float*)d_in[2];
    const float* bg   = (const float*)d_in[3];
    const float* Wa   = (const float*)d_in[4];
    const float* asrc = (const float*)d_in[5];
    const float* adst = (const float*)d_in[6];
    const float* ba   = (const float*)d_in[7];
    const float* Wl   = (const float*)d_in[8];
    const float* bl   = (const float*)d_in[9];
    const float* Wr   = (const float*)d_in[10];
    const float* Wi   = (const float*)d_in[11];
    const float* bi   = (const float*)d_in[12];
    const float* Wo   = (const float*)d_in[13];
    const float* bo   = (const float*)d_in[14];
    float* out = (float*)d_out;

    cudaFuncSetAttribute(k_final_tc, cudaFuncAttributeMaxDynamicSharedMemorySize, KT_SMEM_BYTES);

    void* cnt_ptr = nullptr;
    cudaGetSymbolAddress(&cnt_ptr, g_cnt);
    cudaMemsetAsync(cnt_ptr, 0, (N_NODES + 1) * sizeof(int), 0);

    k_convert<<<2048, 256>>>(ei, x, Wa, asrc, adst);                       // 0
    k_rowassign<<<(N_NODES + 255) / 256, 256>>>();                         // 1
    k_scatter<<<1024, 256>>>();                                            // 2
    k_agg<<<(N_NODES * 32 + 255) / 256, 256>>>(x);                         // 3 (profiled)
    k_final_tc<<<148, 512, KT_SMEM_BYTES>>>(x, Wg, bg, Wa, ba, Wl, bl,     // 4
                                            Wr, Wi, bi, Wo, bo, out);
}